// round 4
// baseline (speedup 1.0000x reference)
#include <cuda_runtime.h>
#include <cstdint>

// Problem constants (fixed by the dataset)
#define FF  512   // input features
#define HD  64    // H1*D1
#define NH  8     // heads layer 1
#define NC  10    // classes / layer-2 width
#define NMAX 50000
#define EMAX 1700000   // E (1.6M) + N self-loops, rounded up
#define SCANB 256      // scan tile
#define NBMAX ((NMAX + SCANB - 1) / SCANB)

// packed f32x2 FMA (Blackwell FFMA2 path; bit-identical IEEE fp32 per lane)
#define FMA2(acc, a, b) \
    asm("fma.rn.f32x2 %0, %1, %2, %0;" : "+l"(acc) : "l"(a), "l"(b))

// -------- scratch (static device globals; no allocation allowed) ----------
static __device__ float g_h1  [NMAX*HD];   // layer-1 projected features
static __device__ float g_as1 [NMAX*NH];   // alpha_src layer 1
static __device__ float g_ad1 [NMAX*NH];   // alpha_dst layer 1
static __device__ float g_h2  [NMAX*NC];   // layer-2 projected features
static __device__ float g_as2 [NMAX];
static __device__ float g_ad2 [NMAX];
static __device__ int   g_cnt [NMAX];      // per-dst degree
static __device__ int   g_off [NMAX+1];    // CSR offsets
static __device__ int   g_cur [NMAX];      // scatter cursors
static __device__ int   g_csr [EMAX];      // CSR src indices (dst-bucketed)
static __device__ int   g_bsum[NBMAX];     // scan block totals -> offsets
static __device__ int   g_is32;            // 1 if edge_index is really int32

// -------- edge dtype sniffer ----------------------------------------------
__global__ void k_detect(const long long* __restrict__ e, long long E, long long N) {
    if (blockIdx.x == 0 && threadIdx.x == 0) {
        int is32 = 0;
        long long cnt = E < 256 ? E : 256;
        for (long long i = 0; i < cnt; i++) {
            long long v = e[i];
            if (v < 0 || v >= N) { is32 = 1; break; }
        }
        g_is32 = is32;
    }
}

// -------- zero degree counters --------------------------------------------
__global__ void k_zero(int N) {
    int i = blockIdx.x * blockDim.x + threadIdx.x;
    if (i < N) g_cnt[i] = 0;
}

// -------- CSR build: histogram --------------------------------------------
__global__ void k_hist(const void* __restrict__ ei, long long E, int N) {
    long long i = (long long)blockIdx.x * blockDim.x + threadIdx.x;
    long long EN = E + (long long)N;
    if (i >= EN) return;
    int d;
    if (i >= E) d = (int)(i - E);
    else if (g_is32) d = ((const int*)ei)[E + i];
    else             d = (int)((const long long*)ei)[E + i];
    atomicAdd(&g_cnt[d], 1);
}

// -------- CSR build: two-level parallel exclusive scan --------------------
__global__ void k_scan1(int N) {
    __shared__ int sh[SCANB];
    int t = threadIdx.x;
    int i = blockIdx.x * SCANB + t;
    int v = (i < N) ? g_cnt[i] : 0;
    sh[t] = v;
    __syncthreads();
    #pragma unroll
    for (int o = 1; o < SCANB; o <<= 1) {
        int u = (t >= o) ? sh[t - o] : 0;
        __syncthreads();
        sh[t] += u;
        __syncthreads();
    }
    if (i < N) g_off[i] = sh[t] - v;
    if (t == SCANB - 1) g_bsum[blockIdx.x] = sh[t];
}

__global__ void k_scan2(int nb) {
    __shared__ int sh[SCANB];
    int t = threadIdx.x;
    int v = (t < nb) ? g_bsum[t] : 0;
    sh[t] = v;
    __syncthreads();
    #pragma unroll
    for (int o = 1; o < SCANB; o <<= 1) {
        int u = (t >= o) ? sh[t - o] : 0;
        __syncthreads();
        sh[t] += u;
        __syncthreads();
    }
    if (t < nb) g_bsum[t] = sh[t] - v;
}

__global__ void k_scan3(int N, int total) {
    int i = blockIdx.x * blockDim.x + threadIdx.x;
    if (i < N) {
        int o = g_off[i] + g_bsum[i / SCANB];
        g_off[i] = o;
        g_cur[i] = o;
    }
    if (i == 0) g_off[N] = total;
}

// -------- CSR build: scatter ----------------------------------------------
__global__ void k_scatter(const void* __restrict__ ei, long long E, int N) {
    long long i = (long long)blockIdx.x * blockDim.x + threadIdx.x;
    long long EN = E + (long long)N;
    if (i >= EN) return;
    int s, d;
    if (i >= E) { s = d = (int)(i - E); }
    else if (g_is32) { const int* p = (const int*)ei; s = p[i]; d = p[E + i]; }
    else { const long long* p = (const long long*)ei; s = (int)p[i]; d = (int)p[E + i]; }
    int pos = atomicAdd(&g_cur[d], 1);
    g_csr[pos] = s;
}

// -------- GEMM1: h1 = x @ W1, fma.rn.f32x2 inner, alpha1 fused ------------
// 64x64 tile, 256 threads, 4x4 micro-tile held as 2x4 f32x2 accumulators.
// A pairs come free (consecutive rows in As); B is stored duplicated so
// (b,b) operands come free. Zero packing instructions in the inner loop.
__global__ void k_gemm1(const float* __restrict__ x, const float* __restrict__ W,
                        const float* __restrict__ a_src, const float* __restrict__ a_dst,
                        int N) {
    __shared__ __align__(16) float  As [32][68];   // [k][m], padded
    __shared__ __align__(16) float2 Bs2[32][64];   // [k][n] duplicated (b,b)
    __shared__ float sAsrc[64], sAdst[64];
    int tid = threadIdx.x;
    if (tid < 64) { sAsrc[tid] = a_src[tid]; sAdst[tid] = a_dst[tid]; }
    int m0  = blockIdx.x * 64;
    int ty  = tid >> 4, tx = tid & 15;
    unsigned long long acc2[2][4] = {};   // [ipair][j]; lo=row 2p, hi=row 2p+1

    for (int kk = 0; kk < FF; kk += 32) {
        #pragma unroll
        for (int j = 0; j < 2; j++) {
            int t4  = tid + 256 * j;
            int row = t4 >> 3, c4 = t4 & 7;
            float4 v = make_float4(0.f, 0.f, 0.f, 0.f);
            if (m0 + row < N)
                v = *(const float4*)&x[(long long)(m0 + row) * FF + kk + c4 * 4];
            As[c4*4+0][row] = v.x; As[c4*4+1][row] = v.y;
            As[c4*4+2][row] = v.z; As[c4*4+3][row] = v.w;
        }
        #pragma unroll
        for (int j = 0; j < 2; j++) {
            int t4 = tid + 256 * j;
            int kr = t4 >> 4, n4 = t4 & 15;
            float4 w = *(const float4*)&W[(kk + kr) * 64 + n4 * 4];
            Bs2[kr][n4*4+0] = make_float2(w.x, w.x);
            Bs2[kr][n4*4+1] = make_float2(w.y, w.y);
            Bs2[kr][n4*4+2] = make_float2(w.z, w.z);
            Bs2[kr][n4*4+3] = make_float2(w.w, w.w);
        }
        __syncthreads();
        #pragma unroll
        for (int k = 0; k < 32; k++) {
            ulonglong2 av  = *(const ulonglong2*)&As [k][ty * 4]; // (a0,a1),(a2,a3)
            ulonglong2 bv0 = *(const ulonglong2*)&Bs2[k][tx * 4]; // (b0,b0),(b1,b1)
            ulonglong2 bv1 = *(const ulonglong2*)&Bs2[k][tx * 4 + 2];
            FMA2(acc2[0][0], av.x, bv0.x); FMA2(acc2[0][1], av.x, bv0.y);
            FMA2(acc2[0][2], av.x, bv1.x); FMA2(acc2[0][3], av.x, bv1.y);
            FMA2(acc2[1][0], av.y, bv0.x); FMA2(acc2[1][1], av.y, bv0.y);
            FMA2(acc2[1][2], av.y, bv1.x); FMA2(acc2[1][3], av.y, bv1.y);
        }
        __syncthreads();
    }
    // Unpack accumulators
    float acc[4][4];
    #pragma unroll
    for (int p = 0; p < 2; p++)
        #pragma unroll
        for (int j = 0; j < 4; j++) {
            float2 f = *(float2*)&acc2[p][j];
            acc[2*p][j] = f.x; acc[2*p+1][j] = f.y;
        }
    // Epilogue: store h1 + fused alpha_src/alpha_dst projections.
    int h = tx >> 1, base = h * 8 + (tx & 1) * 4;
    #pragma unroll
    for (int i = 0; i < 4; i++) {
        int row = m0 + ty * 4 + i;
        float s = 0.f, dd = 0.f;
        #pragma unroll
        for (int j = 0; j < 4; j++) {
            s  += acc[i][j] * sAsrc[base + j];
            dd += acc[i][j] * sAdst[base + j];
        }
        float s2 = __shfl_xor_sync(0xffffffffu, s, 1);
        float d2 = __shfl_xor_sync(0xffffffffu, dd, 1);
        if (row < N) {
            #pragma unroll
            for (int j = 0; j < 4; j++)
                g_h1[row * 64 + tx * 4 + j] = acc[i][j];
            if (!(tx & 1)) {
                g_as1[row * 8 + h] = s + s2;
                g_ad1[row * 8 + h] = dd + d2;
            }
        }
    }
}

// -------- layer-1 aggregation + layer-2 GEMM + alpha2, fused --------------
// Warp per dst. CSR gather, register softmax-aggregation (no atomics),
// normalize+bias+ELU, then the 64->10 projection + alpha2 via warp reduce.
__global__ void k_agg1(const float* __restrict__ b1,
                       const float* __restrict__ W2,
                       const float* __restrict__ a_src2,
                       const float* __restrict__ a_dst2, int N) {
    int d = (blockIdx.x * blockDim.x + threadIdx.x) >> 5;
    int lane = threadIdx.x & 31;
    if (d >= N) return;

    // Preload W2 rows for this lane's two features (hidden under the loop)
    float w2a[NC], w2b[NC];
    #pragma unroll
    for (int c = 0; c < NC; c++) {
        w2a[c] = W2[lane * NC + c];
        w2b[c] = W2[(lane + 32) * NC + c];
    }

    int beg = g_off[d], end = g_off[d + 1];
    float ad_l = (lane < NH) ? g_ad1[d * NH + lane] : 0.f;
    float acc0 = 0.f, acc1 = 0.f, den = 0.f;

    int i = beg;
    for (; i + 2 <= end; i += 2) {           // unroll x2 for gather MLP
        int s0 = g_csr[i], s1 = g_csr[i + 1];
        float w0 = 0.f, w1 = 0.f;
        if (lane < NH) {
            float e0 = g_as1[s0 * NH + lane] + ad_l;
            float e1 = g_as1[s1 * NH + lane] + ad_l;
            e0 = e0 > 0.f ? e0 : 0.2f * e0;
            e1 = e1 > 0.f ? e1 : 0.2f * e1;
            w0 = __expf(e0); w1 = __expf(e1);
            den += w0 + w1;
        }
        float wa0 = __shfl_sync(0xffffffffu, w0, lane >> 3);
        float wb0 = __shfl_sync(0xffffffffu, w0, (lane >> 3) + 4);
        float wa1 = __shfl_sync(0xffffffffu, w1, lane >> 3);
        float wb1 = __shfl_sync(0xffffffffu, w1, (lane >> 3) + 4);
        float h0a = g_h1[s0 * 64 + lane],      h1a = g_h1[s1 * 64 + lane];
        float h0b = g_h1[s0 * 64 + 32 + lane], h1b = g_h1[s1 * 64 + 32 + lane];
        acc0 += wa0 * h0a + wa1 * h1a;
        acc1 += wb0 * h0b + wb1 * h1b;
    }
    if (i < end) {
        int s = g_csr[i];
        float w = 0.f;
        if (lane < NH) {
            float e = g_as1[s * NH + lane] + ad_l;
            e = e > 0.f ? e : 0.2f * e;
            w = __expf(e);
            den += w;
        }
        float wa = __shfl_sync(0xffffffffu, w, lane >> 3);
        float wb = __shfl_sync(0xffffffffu, w, (lane >> 3) + 4);
        acc0 += wa * g_h1[s * 64 + lane];
        acc1 += wb * g_h1[s * 64 + 32 + lane];
    }

    float dena = __shfl_sync(0xffffffffu, den, lane >> 3);
    float denb = __shfl_sync(0xffffffffu, den, (lane >> 3) + 4);
    float v0 = acc0 / dena + b1[lane];
    float v1 = acc1 / denb + b1[32 + lane];
    v0 = v0 > 0.f ? v0 : expm1f(v0);         // ELU
    v1 = v1 > 0.f ? v1 : expm1f(v1);

    // Fused layer-2 projection: h2[c] = sum_f x2[f] * W2[f][c]
    float asum = 0.f, adsum = 0.f;
    #pragma unroll
    for (int c = 0; c < NC; c++) {
        float s = v0 * w2a[c] + v1 * w2b[c];
        #pragma unroll
        for (int o = 16; o; o >>= 1) s += __shfl_down_sync(0xffffffffu, s, o);
        if (lane == 0) {
            g_h2[d * NC + c] = s;
            asum  += s * a_src2[c];
            adsum += s * a_dst2[c];
        }
    }
    if (lane == 0) { g_as2[d] = asum; g_ad2[d] = adsum; }
}

// -------- aggregation layer 2 (warp per dst, lanes over edges) ------------
__global__ void k_agg2(const float* __restrict__ b2, float* __restrict__ out, int N) {
    int d = (blockIdx.x * blockDim.x + threadIdx.x) >> 5;
    int lane = threadIdx.x & 31;
    if (d >= N) return;
    int beg = g_off[d], end = g_off[d + 1];
    float ad_d = g_ad2[d];
    float acc[NC] = {};
    float den = 0.f;
    for (int i = beg + lane; i < end; i += 32) {
        int s = g_csr[i];
        float e = g_as2[s] + ad_d;
        e = e > 0.f ? e : 0.2f * e;
        float w = __expf(e);
        den += w;
        const float* hp = &g_h2[s * NC];
        #pragma unroll
        for (int c = 0; c < NC; c++) acc[c] += w * hp[c];
    }
    #pragma unroll
    for (int o = 16; o; o >>= 1) {
        den += __shfl_down_sync(0xffffffffu, den, o);
        #pragma unroll
        for (int c = 0; c < NC; c++)
            acc[c] += __shfl_down_sync(0xffffffffu, acc[c], o);
    }
    if (lane == 0) {
        float inv = 1.f / den;
        float v[NC], m = -1e30f;
        #pragma unroll
        for (int c = 0; c < NC; c++) {
            v[c] = acc[c] * inv + b2[c];
            m = fmaxf(m, v[c]);
        }
        float ssum = 0.f;
        #pragma unroll
        for (int c = 0; c < NC; c++) ssum += __expf(v[c] - m);
        float l = __logf(ssum);
        #pragma unroll
        for (int c = 0; c < NC; c++) out[d * NC + c] = v[c] - m - l;
    }
}

// ---------------------------------------------------------------------------
extern "C" void kernel_launch(void* const* d_in, const int* in_sizes, int n_in,
                              void* d_out, int out_size) {
    const float* x   = (const float*)d_in[0];
    const void*  ei  = d_in[1];
    const float* W1  = (const float*)d_in[2];
    const float* as1 = (const float*)d_in[3];
    const float* ad1 = (const float*)d_in[4];
    const float* b1  = (const float*)d_in[5];
    const float* W2  = (const float*)d_in[6];
    const float* as2 = (const float*)d_in[7];
    const float* ad2 = (const float*)d_in[8];
    const float* b2  = (const float*)d_in[9];

    int       N  = in_sizes[0] / FF;           // 50000
    long long E  = (long long)in_sizes[1] / 2; // 1.6M
    long long EN = E + (long long)N;
    int nb = (N + SCANB - 1) / SCANB;
    float* out = (float*)d_out;

    k_detect<<<1, 32>>>((const long long*)ei, E, N);
    k_zero<<<(N + 255) / 256, 256>>>(N);
    k_hist<<<(unsigned)((EN + 255) / 256), 256>>>(ei, E, N);
    k_scan1<<<nb, SCANB>>>(N);
    k_scan2<<<1, SCANB>>>(nb);
    k_scan3<<<nb, SCANB>>>(N, (int)EN);
    k_scatter<<<(unsigned)((EN + 255) / 256), 256>>>(ei, E, N);
    k_gemm1<<<(N + 63) / 64, 256>>>(x, W1, as1, ad1, N);
    k_agg1<<<(unsigned)(((long long)N * 32 + 255) / 256), 256>>>(b1, W2, as2, ad2, N);
    k_agg2<<<(unsigned)(((long long)N * 32 + 255) / 256), 256>>>(b2, out, N);
}

// round 5
// speedup vs baseline: 1.4403x; 1.4403x over previous
#include <cuda_runtime.h>
#include <cstdint>

// Problem constants (fixed by the dataset)
#define FF  512   // input features
#define HD  64    // H1*D1
#define NH  8     // heads layer 1
#define NC  10    // classes / layer-2 width
#define NMAX 50000
#define EMAX 1700000   // E (1.6M) + N self-loops, rounded up
#define SCANB 256      // scan tile
#define NBMAX ((NMAX + SCANB - 1) / SCANB)

// -------- scratch (static device globals; no allocation allowed) ----------
static __device__ float g_h1  [NMAX*HD];   // layer-1 projected features
static __device__ float g_as1 [NMAX*NH];   // alpha_src layer 1
static __device__ float g_ad1 [NMAX*NH];   // alpha_dst layer 1
static __device__ float g_h2  [NMAX*NC];   // layer-2 projected features
static __device__ float g_as2 [NMAX];
static __device__ float g_ad2 [NMAX];
static __device__ int   g_cnt [NMAX];      // per-dst degree
static __device__ int   g_off [NMAX+1];    // CSR offsets
static __device__ int   g_cur [NMAX];      // scatter cursors
static __device__ int   g_csr [EMAX];      // CSR src indices (dst-bucketed)
static __device__ int   g_bsum[NBMAX];     // scan block totals -> offsets
static __device__ int   g_is32;            // 1 if edge_index is really int32

// -------- edge dtype sniffer ----------------------------------------------
__global__ void k_detect(const long long* __restrict__ e, long long E, long long N) {
    if (blockIdx.x == 0 && threadIdx.x == 0) {
        int is32 = 0;
        long long cnt = E < 256 ? E : 256;
        for (long long i = 0; i < cnt; i++) {
            long long v = e[i];
            if (v < 0 || v >= N) { is32 = 1; break; }
        }
        g_is32 = is32;
    }
}

// -------- zero degree counters --------------------------------------------
__global__ void k_zero(int N) {
    int i = blockIdx.x * blockDim.x + threadIdx.x;
    if (i < N) g_cnt[i] = 0;
}

// -------- CSR build: histogram --------------------------------------------
__global__ void k_hist(const void* __restrict__ ei, long long E, int N) {
    long long i = (long long)blockIdx.x * blockDim.x + threadIdx.x;
    long long EN = E + (long long)N;
    if (i >= EN) return;
    int d;
    if (i >= E) d = (int)(i - E);
    else if (g_is32) d = ((const int*)ei)[E + i];
    else             d = (int)((const long long*)ei)[E + i];
    atomicAdd(&g_cnt[d], 1);
}

// -------- CSR build: two-level parallel exclusive scan --------------------
__global__ void k_scan1(int N) {
    __shared__ int sh[SCANB];
    int t = threadIdx.x;
    int i = blockIdx.x * SCANB + t;
    int v = (i < N) ? g_cnt[i] : 0;
    sh[t] = v;
    __syncthreads();
    #pragma unroll
    for (int o = 1; o < SCANB; o <<= 1) {
        int u = (t >= o) ? sh[t - o] : 0;
        __syncthreads();
        sh[t] += u;
        __syncthreads();
    }
    if (i < N) g_off[i] = sh[t] - v;
    if (t == SCANB - 1) g_bsum[blockIdx.x] = sh[t];
}

__global__ void k_scan2(int nb) {
    __shared__ int sh[SCANB];
    int t = threadIdx.x;
    int v = (t < nb) ? g_bsum[t] : 0;
    sh[t] = v;
    __syncthreads();
    #pragma unroll
    for (int o = 1; o < SCANB; o <<= 1) {
        int u = (t >= o) ? sh[t - o] : 0;
        __syncthreads();
        sh[t] += u;
        __syncthreads();
    }
    if (t < nb) g_bsum[t] = sh[t] - v;
}

__global__ void k_scan3(int N, int total) {
    int i = blockIdx.x * blockDim.x + threadIdx.x;
    if (i < N) {
        int o = g_off[i] + g_bsum[i / SCANB];
        g_off[i] = o;
        g_cur[i] = o;
    }
    if (i == 0) g_off[N] = total;
}

// -------- CSR build: scatter ----------------------------------------------
__global__ void k_scatter(const void* __restrict__ ei, long long E, int N) {
    long long i = (long long)blockIdx.x * blockDim.x + threadIdx.x;
    long long EN = E + (long long)N;
    if (i >= EN) return;
    int s, d;
    if (i >= E) { s = d = (int)(i - E); }
    else if (g_is32) { const int* p = (const int*)ei; s = p[i]; d = p[E + i]; }
    else { const long long* p = (const long long*)ei; s = (int)p[i]; d = (int)p[E + i]; }
    int pos = atomicAdd(&g_cur[d], 1);
    g_csr[pos] = s;
}

// -------- GEMM1: h1 = x @ W1  [N,512]x[512,64], alpha1 fused in epilogue --
// 64x64 output tile per block, 256 threads, 4x4 register micro-tile.
// (Plain FFMA version — the R3 config measured at FFMA-issue saturation.)
__global__ void k_gemm1(const float* __restrict__ x, const float* __restrict__ W,
                        const float* __restrict__ a_src, const float* __restrict__ a_dst,
                        int N) {
    __shared__ float As[32][68];   // [k][m], padded
    __shared__ float Bs[32][64];   // [k][n]
    __shared__ float sAsrc[64], sAdst[64];
    int tid = threadIdx.x;
    if (tid < 64) { sAsrc[tid] = a_src[tid]; sAdst[tid] = a_dst[tid]; }
    int m0  = blockIdx.x * 64;
    int ty  = tid >> 4, tx = tid & 15;
    float acc[4][4] = {};

    for (int kk = 0; kk < FF; kk += 32) {
        #pragma unroll
        for (int j = 0; j < 2; j++) {
            int t4  = tid + 256 * j;
            int row = t4 >> 3, c4 = t4 & 7;
            float4 v = make_float4(0.f, 0.f, 0.f, 0.f);
            if (m0 + row < N)
                v = *(const float4*)&x[(long long)(m0 + row) * FF + kk + c4 * 4];
            As[c4*4+0][row] = v.x; As[c4*4+1][row] = v.y;
            As[c4*4+2][row] = v.z; As[c4*4+3][row] = v.w;
        }
        #pragma unroll
        for (int j = 0; j < 2; j++) {
            int t4 = tid + 256 * j;
            int kr = t4 >> 4, n4 = t4 & 15;
            *(float4*)&Bs[kr][n4*4] = *(const float4*)&W[(kk + kr) * 64 + n4 * 4];
        }
        __syncthreads();
        #pragma unroll
        for (int k = 0; k < 32; k++) {
            float4 a = *(const float4*)&As[k][ty * 4];
            float4 b = *(const float4*)&Bs[k][tx * 4];
            float av[4] = {a.x, a.y, a.z, a.w};
            float bv[4] = {b.x, b.y, b.z, b.w};
            #pragma unroll
            for (int i = 0; i < 4; i++)
                #pragma unroll
                for (int j = 0; j < 4; j++)
                    acc[i][j] += av[i] * bv[j];
        }
        __syncthreads();
    }
    // Epilogue: store h1 + fused alpha_src/alpha_dst projections.
    int h = tx >> 1, base = h * 8 + (tx & 1) * 4;
    #pragma unroll
    for (int i = 0; i < 4; i++) {
        int row = m0 + ty * 4 + i;
        float s = 0.f, dd = 0.f;
        #pragma unroll
        for (int j = 0; j < 4; j++) {
            s  += acc[i][j] * sAsrc[base + j];
            dd += acc[i][j] * sAdst[base + j];
        }
        float s2 = __shfl_xor_sync(0xffffffffu, s, 1);
        float d2 = __shfl_xor_sync(0xffffffffu, dd, 1);
        if (row < N) {
            #pragma unroll
            for (int j = 0; j < 4; j++)
                g_h1[row * 64 + tx * 4 + j] = acc[i][j];
            if (!(tx & 1)) {
                g_as1[row * 8 + h] = s + s2;
                g_ad1[row * 8 + h] = dd + d2;
            }
        }
    }
}

// -------- layer-1 aggregation + layer-2 GEMM + alpha2, fused --------------
// Warp per dst. CSR gather, register softmax-aggregation (no atomics),
// normalize+bias+ELU, then the 64->10 projection + alpha2 via warp reduce.
__global__ void k_agg1(const float* __restrict__ b1,
                       const float* __restrict__ W2,
                       const float* __restrict__ a_src2,
                       const float* __restrict__ a_dst2, int N) {
    int d = (blockIdx.x * blockDim.x + threadIdx.x) >> 5;
    int lane = threadIdx.x & 31;
    if (d >= N) return;

    // Preload W2 rows for this lane's two features (hidden under the loop)
    float w2a[NC], w2b[NC];
    #pragma unroll
    for (int c = 0; c < NC; c++) {
        w2a[c] = W2[lane * NC + c];
        w2b[c] = W2[(lane + 32) * NC + c];
    }

    int beg = g_off[d], end = g_off[d + 1];
    float ad_l = (lane < NH) ? g_ad1[d * NH + lane] : 0.f;
    float acc0 = 0.f, acc1 = 0.f, den = 0.f;

    int i = beg;
    for (; i + 2 <= end; i += 2) {           // unroll x2 for gather MLP
        int s0 = g_csr[i], s1 = g_csr[i + 1];
        float w0 = 0.f, w1 = 0.f;
        if (lane < NH) {
            float e0 = g_as1[s0 * NH + lane] + ad_l;
            float e1 = g_as1[s1 * NH + lane] + ad_l;
            e0 = e0 > 0.f ? e0 : 0.2f * e0;
            e1 = e1 > 0.f ? e1 : 0.2f * e1;
            w0 = __expf(e0); w1 = __expf(e1);
            den += w0 + w1;
        }
        float wa0 = __shfl_sync(0xffffffffu, w0, lane >> 3);
        float wb0 = __shfl_sync(0xffffffffu, w0, (lane >> 3) + 4);
        float wa1 = __shfl_sync(0xffffffffu, w1, lane >> 3);
        float wb1 = __shfl_sync(0xffffffffu, w1, (lane >> 3) + 4);
        float h0a = g_h1[s0 * 64 + lane],      h1a = g_h1[s1 * 64 + lane];
        float h0b = g_h1[s0 * 64 + 32 + lane], h1b = g_h1[s1 * 64 + 32 + lane];
        acc0 += wa0 * h0a + wa1 * h1a;
        acc1 += wb0 * h0b + wb1 * h1b;
    }
    if (i < end) {
        int s = g_csr[i];
        float w = 0.f;
        if (lane < NH) {
            float e = g_as1[s * NH + lane] + ad_l;
            e = e > 0.f ? e : 0.2f * e;
            w = __expf(e);
            den += w;
        }
        float wa = __shfl_sync(0xffffffffu, w, lane >> 3);
        float wb = __shfl_sync(0xffffffffu, w, (lane >> 3) + 4);
        acc0 += wa * g_h1[s * 64 + lane];
        acc1 += wb * g_h1[s * 64 + 32 + lane];
    }

    float dena = __shfl_sync(0xffffffffu, den, lane >> 3);
    float denb = __shfl_sync(0xffffffffu, den, (lane >> 3) + 4);
    float v0 = acc0 / dena + b1[lane];
    float v1 = acc1 / denb + b1[32 + lane];
    v0 = v0 > 0.f ? v0 : expm1f(v0);         // ELU
    v1 = v1 > 0.f ? v1 : expm1f(v1);

    // Fused layer-2 projection: h2[c] = sum_f x2[f] * W2[f][c]
    float asum = 0.f, adsum = 0.f;
    #pragma unroll
    for (int c = 0; c < NC; c++) {
        float s = v0 * w2a[c] + v1 * w2b[c];
        #pragma unroll
        for (int o = 16; o; o >>= 1) s += __shfl_down_sync(0xffffffffu, s, o);
        if (lane == 0) {
            g_h2[d * NC + c] = s;
            asum  += s * a_src2[c];
            adsum += s * a_dst2[c];
        }
    }
    if (lane == 0) { g_as2[d] = asum; g_ad2[d] = adsum; }
}

// -------- aggregation layer 2 (warp per dst, lanes over edges) ------------
__global__ void k_agg2(const float* __restrict__ b2, float* __restrict__ out, int N) {
    int d = (blockIdx.x * blockDim.x + threadIdx.x) >> 5;
    int lane = threadIdx.x & 31;
    if (d >= N) return;
    int beg = g_off[d], end = g_off[d + 1];
    float ad_d = g_ad2[d];
    float acc[NC] = {};
    float den = 0.f;
    for (int i = beg + lane; i < end; i += 32) {
        int s = g_csr[i];
        float e = g_as2[s] + ad_d;
        e = e > 0.f ? e : 0.2f * e;
        float w = __expf(e);
        den += w;
        const float* hp = &g_h2[s * NC];
        #pragma unroll
        for (int c = 0; c < NC; c++) acc[c] += w * hp[c];
    }
    #pragma unroll
    for (int o = 16; o; o >>= 1) {
        den += __shfl_down_sync(0xffffffffu, den, o);
        #pragma unroll
        for (int c = 0; c < NC; c++)
            acc[c] += __shfl_down_sync(0xffffffffu, acc[c], o);
    }
    if (lane == 0) {
        float inv = 1.f / den;
        float v[NC], m = -1e30f;
        #pragma unroll
        for (int c = 0; c < NC; c++) {
            v[c] = acc[c] * inv + b2[c];
            m = fmaxf(m, v[c]);
        }
        float ssum = 0.f;
        #pragma unroll
        for (int c = 0; c < NC; c++) ssum += __expf(v[c] - m);
        float l = __logf(ssum);
        #pragma unroll
        for (int c = 0; c < NC; c++) out[d * NC + c] = v[c] - m - l;
    }
}

// ---------------------------------------------------------------------------
extern "C" void kernel_launch(void* const* d_in, const int* in_sizes, int n_in,
                              void* d_out, int out_size) {
    const float* x   = (const float*)d_in[0];
    const void*  ei  = d_in[1];
    const float* W1  = (const float*)d_in[2];
    const float* as1 = (const float*)d_in[3];
    const float* ad1 = (const float*)d_in[4];
    const float* b1  = (const float*)d_in[5];
    const float* W2  = (const float*)d_in[6];
    const float* as2 = (const float*)d_in[7];
    const float* ad2 = (const float*)d_in[8];
    const float* b2  = (const float*)d_in[9];

    int       N  = in_sizes[0] / FF;           // 50000
    long long E  = (long long)in_sizes[1] / 2; // 1.6M
    long long EN = E + (long long)N;
    int nb = (N + SCANB - 1) / SCANB;
    float* out = (float*)d_out;

    k_detect<<<1, 32>>>((const long long*)ei, E, N);
    k_zero<<<(N + 255) / 256, 256>>>(N);
    k_hist<<<(unsigned)((EN + 255) / 256), 256>>>(ei, E, N);
    k_scan1<<<nb, SCANB>>>(N);
    k_scan2<<<1, SCANB>>>(nb);
    k_scan3<<<nb, SCANB>>>(N, (int)EN);
    k_scatter<<<(unsigned)((EN + 255) / 256), 256>>>(ei, E, N);
    k_gemm1<<<(N + 63) / 64, 256>>>(x, W1, as1, ad1, N);
    k_agg1<<<(unsigned)(((long long)N * 32 + 255) / 256), 256>>>(b1, W2, as2, ad2, N);
    k_agg2<<<(unsigned)(((long long)N * 32 + 255) / 256), 256>>>(b2, out, N);
}

// round 6
// speedup vs baseline: 1.6557x; 1.1496x over previous
#include <cuda_runtime.h>
#include <cstdint>

// Problem constants (fixed by the dataset)
#define FF  512   // input features
#define HD  64    // H1*D1
#define NH  8     // heads layer 1
#define NC  10    // classes / layer-2 width
#define NMAX 50000
#define EMAX 1700000   // E (1.6M) + N self-loops, rounded up
#define SCANB 256      // scan tile
#define NBMAX ((NMAX + SCANB - 1) / SCANB)

// -------- scratch (static device globals; no allocation allowed) ----------
static __device__ float g_h1  [NMAX*HD];   // layer-1 projected features
static __device__ float g_as1 [NMAX*NH];   // alpha_src layer 1
static __device__ float g_ad1 [NMAX*NH];   // alpha_dst layer 1
static __device__ float g_x2  [NMAX*HD];   // elu(layer-1 output) = layer-2 input
static __device__ float g_h2  [NMAX*NC];   // layer-2 projected features
static __device__ float g_as2 [NMAX];
static __device__ float g_ad2 [NMAX];
static __device__ int   g_cnt [NMAX];      // per-dst degree
static __device__ int   g_off [NMAX+1];    // CSR offsets
static __device__ int   g_cur [NMAX];      // scatter cursors
static __device__ int   g_csr [EMAX];      // CSR src indices (dst-bucketed)
static __device__ int   g_bsum[NBMAX];     // scan block totals -> offsets
static __device__ int   g_is32;            // 1 if edge_index is really int32

// -------- edge dtype sniffer ----------------------------------------------
__global__ void k_detect(const long long* __restrict__ e, long long E, long long N) {
    if (blockIdx.x == 0 && threadIdx.x == 0) {
        int is32 = 0;
        long long cnt = E < 256 ? E : 256;
        for (long long i = 0; i < cnt; i++) {
            long long v = e[i];
            if (v < 0 || v >= N) { is32 = 1; break; }
        }
        g_is32 = is32;
    }
}

// -------- zero degree counters --------------------------------------------
__global__ void k_zero(int N) {
    int i = blockIdx.x * blockDim.x + threadIdx.x;
    if (i < N) g_cnt[i] = 0;
}

// -------- CSR build: histogram --------------------------------------------
__global__ void k_hist(const void* __restrict__ ei, long long E, int N) {
    long long i = (long long)blockIdx.x * blockDim.x + threadIdx.x;
    long long EN = E + (long long)N;
    if (i >= EN) return;
    int d;
    if (i >= E) d = (int)(i - E);
    else if (g_is32) d = ((const int*)ei)[E + i];
    else             d = (int)((const long long*)ei)[E + i];
    atomicAdd(&g_cnt[d], 1);
}

// -------- CSR build: two-level parallel exclusive scan --------------------
__global__ void k_scan1(int N) {
    __shared__ int sh[SCANB];
    int t = threadIdx.x;
    int i = blockIdx.x * SCANB + t;
    int v = (i < N) ? g_cnt[i] : 0;
    sh[t] = v;
    __syncthreads();
    #pragma unroll
    for (int o = 1; o < SCANB; o <<= 1) {
        int u = (t >= o) ? sh[t - o] : 0;
        __syncthreads();
        sh[t] += u;
        __syncthreads();
    }
    if (i < N) g_off[i] = sh[t] - v;
    if (t == SCANB - 1) g_bsum[blockIdx.x] = sh[t];
}

__global__ void k_scan2(int nb) {
    __shared__ int sh[SCANB];
    int t = threadIdx.x;
    int v = (t < nb) ? g_bsum[t] : 0;
    sh[t] = v;
    __syncthreads();
    #pragma unroll
    for (int o = 1; o < SCANB; o <<= 1) {
        int u = (t >= o) ? sh[t - o] : 0;
        __syncthreads();
        sh[t] += u;
        __syncthreads();
    }
    if (t < nb) g_bsum[t] = sh[t] - v;
}

__global__ void k_scan3(int N, int total) {
    int i = blockIdx.x * blockDim.x + threadIdx.x;
    if (i < N) {
        int o = g_off[i] + g_bsum[i / SCANB];
        g_off[i] = o;
        g_cur[i] = o;
    }
    if (i == 0) g_off[N] = total;
}

// -------- CSR build: scatter ----------------------------------------------
__global__ void k_scatter(const void* __restrict__ ei, long long E, int N) {
    long long i = (long long)blockIdx.x * blockDim.x + threadIdx.x;
    long long EN = E + (long long)N;
    if (i >= EN) return;
    int s, d;
    if (i >= E) { s = d = (int)(i - E); }
    else if (g_is32) { const int* p = (const int*)ei; s = p[i]; d = p[E + i]; }
    else { const long long* p = (const long long*)ei; s = (int)p[i]; d = (int)p[E + i]; }
    int pos = atomicAdd(&g_cur[d], 1);
    g_csr[pos] = s;
}

// -------- GEMM1: h1 = x @ W1  [N,512]x[512,64], alpha1 fused in epilogue --
// 64x64 output tile per block, 256 threads, 4x4 register micro-tile.
// (Exact R3 configuration — measured at FFMA-issue saturation.)
__global__ void k_gemm1(const float* __restrict__ x, const float* __restrict__ W,
                        const float* __restrict__ a_src, const float* __restrict__ a_dst,
                        int N) {
    __shared__ float As[32][68];   // [k][m], padded
    __shared__ float Bs[32][64];   // [k][n]
    __shared__ float sAsrc[64], sAdst[64];
    int tid = threadIdx.x;
    if (tid < 64) { sAsrc[tid] = a_src[tid]; sAdst[tid] = a_dst[tid]; }
    int m0  = blockIdx.x * 64;
    int ty  = tid >> 4, tx = tid & 15;
    float acc[4][4] = {};

    for (int kk = 0; kk < FF; kk += 32) {
        #pragma unroll
        for (int j = 0; j < 2; j++) {
            int t4  = tid + 256 * j;
            int row = t4 >> 3, c4 = t4 & 7;
            float4 v = make_float4(0.f, 0.f, 0.f, 0.f);
            if (m0 + row < N)
                v = *(const float4*)&x[(long long)(m0 + row) * FF + kk + c4 * 4];
            As[c4*4+0][row] = v.x; As[c4*4+1][row] = v.y;
            As[c4*4+2][row] = v.z; As[c4*4+3][row] = v.w;
        }
        #pragma unroll
        for (int j = 0; j < 2; j++) {
            int t4 = tid + 256 * j;
            int kr = t4 >> 4, n4 = t4 & 15;
            *(float4*)&Bs[kr][n4*4] = *(const float4*)&W[(kk + kr) * 64 + n4 * 4];
        }
        __syncthreads();
        #pragma unroll
        for (int k = 0; k < 32; k++) {
            float4 a = *(const float4*)&As[k][ty * 4];
            float4 b = *(const float4*)&Bs[k][tx * 4];
            float av[4] = {a.x, a.y, a.z, a.w};
            float bv[4] = {b.x, b.y, b.z, b.w};
            #pragma unroll
            for (int i = 0; i < 4; i++)
                #pragma unroll
                for (int j = 0; j < 4; j++)
                    acc[i][j] += av[i] * bv[j];
        }
        __syncthreads();
    }
    // Epilogue: store h1 + fused alpha_src/alpha_dst projections.
    int h = tx >> 1, base = h * 8 + (tx & 1) * 4;
    #pragma unroll
    for (int i = 0; i < 4; i++) {
        int row = m0 + ty * 4 + i;
        float s = 0.f, dd = 0.f;
        #pragma unroll
        for (int j = 0; j < 4; j++) {
            s  += acc[i][j] * sAsrc[base + j];
            dd += acc[i][j] * sAdst[base + j];
        }
        float s2 = __shfl_xor_sync(0xffffffffu, s, 1);
        float d2 = __shfl_xor_sync(0xffffffffu, dd, 1);
        if (row < N) {
            #pragma unroll
            for (int j = 0; j < 4; j++)
                g_h1[row * 64 + tx * 4 + j] = acc[i][j];
            if (!(tx & 1)) {
                g_as1[row * 8 + h] = s + s2;
                g_ad1[row * 8 + h] = dd + d2;
            }
        }
    }
}

// -------- aggregation layer 1 (warp per dst, CSR, no atomics) -------------
// float2 lane layout: lane covers features 2*lane, 2*lane+1 (same head,
// head = lane>>2). One LDG.64 + one shuffle per edge per lane (was 2+2).
__global__ void k_agg1(const float* __restrict__ b1, int N) {
    int d = (blockIdx.x * blockDim.x + threadIdx.x) >> 5;
    int lane = threadIdx.x & 31;
    if (d >= N) return;
    int beg = g_off[d], end = g_off[d + 1];
    float ad_l = (lane < NH) ? g_ad1[d * NH + lane] : 0.f;
    float accx = 0.f, accy = 0.f, den = 0.f;
    for (int i = beg; i < end; i++) {
        int s = g_csr[i];
        float w = 0.f;
        if (lane < NH) {
            float e = g_as1[s * NH + lane] + ad_l;
            e = e > 0.f ? e : 0.2f * e;          // LeakyReLU(0.2)
            w = __expf(e);
            den += w;
        }
        float wl = __shfl_sync(0xffffffffu, w, lane >> 2);   // head of 2*lane
        float2 hv = *(const float2*)&g_h1[s * 64 + lane * 2];
        accx += wl * hv.x;
        accy += wl * hv.y;
    }
    float denl = __shfl_sync(0xffffffffu, den, lane >> 2);
    float v0 = accx / denl + b1[2 * lane];
    float v1 = accy / denl + b1[2 * lane + 1];
    v0 = v0 > 0.f ? v0 : expm1f(v0);         // ELU
    v1 = v1 > 0.f ? v1 : expm1f(v1);
    *(float2*)&g_x2[d * 64 + 2 * lane] = make_float2(v0, v1);
}

// -------- GEMM2 + alpha projections layer 2 (warp per node) ---------------
__global__ void k_gemm2(const float* __restrict__ W2,
                        const float* __restrict__ a_src2,
                        const float* __restrict__ a_dst2, int N) {
    int wid = (blockIdx.x * blockDim.x + threadIdx.x) >> 5;
    int lane = threadIdx.x & 31;
    if (wid >= N) return;
    float v0 = g_x2[wid * 64 + lane];
    float v1 = g_x2[wid * 64 + 32 + lane];
    float asum = 0.f, adsum = 0.f;
    #pragma unroll
    for (int c = 0; c < NC; c++) {
        float s = v0 * W2[lane * NC + c] + v1 * W2[(lane + 32) * NC + c];
        #pragma unroll
        for (int o = 16; o; o >>= 1) s += __shfl_down_sync(0xffffffffu, s, o);
        if (lane == 0) {
            g_h2[wid * NC + c] = s;
            asum  += s * a_src2[c];
            adsum += s * a_dst2[c];
        }
    }
    if (lane == 0) { g_as2[wid] = asum; g_ad2[wid] = adsum; }
}

// -------- aggregation layer 2 (warp per dst, lanes over edges) ------------
__global__ void k_agg2(const float* __restrict__ b2, float* __restrict__ out, int N) {
    int d = (blockIdx.x * blockDim.x + threadIdx.x) >> 5;
    int lane = threadIdx.x & 31;
    if (d >= N) return;
    int beg = g_off[d], end = g_off[d + 1];
    float ad_d = g_ad2[d];
    float acc[NC] = {};
    float den = 0.f;
    for (int i = beg + lane; i < end; i += 32) {
        int s = g_csr[i];
        float e = g_as2[s] + ad_d;
        e = e > 0.f ? e : 0.2f * e;
        float w = __expf(e);
        den += w;
        const float* hp = &g_h2[s * NC];
        #pragma unroll
        for (int c = 0; c < NC; c++) acc[c] += w * hp[c];
    }
    #pragma unroll
    for (int o = 16; o; o >>= 1) {
        den += __shfl_down_sync(0xffffffffu, den, o);
        #pragma unroll
        for (int c = 0; c < NC; c++)
            acc[c] += __shfl_down_sync(0xffffffffu, acc[c], o);
    }
    if (lane == 0) {
        float inv = 1.f / den;
        float v[NC], m = -1e30f;
        #pragma unroll
        for (int c = 0; c < NC; c++) {
            v[c] = acc[c] * inv + b2[c];
            m = fmaxf(m, v[c]);
        }
        float ssum = 0.f;
        #pragma unroll
        for (int c = 0; c < NC; c++) ssum += __expf(v[c] - m);
        float l = __logf(ssum);
        #pragma unroll
        for (int c = 0; c < NC; c++) out[d * NC + c] = v[c] - m - l;
    }
}

// ---------------------------------------------------------------------------
extern "C" void kernel_launch(void* const* d_in, const int* in_sizes, int n_in,
                              void* d_out, int out_size) {
    const float* x   = (const float*)d_in[0];
    const void*  ei  = d_in[1];
    const float* W1  = (const float*)d_in[2];
    const float* as1 = (const float*)d_in[3];
    const float* ad1 = (const float*)d_in[4];
    const float* b1  = (const float*)d_in[5];
    const float* W2  = (const float*)d_in[6];
    const float* as2 = (const float*)d_in[7];
    const float* ad2 = (const float*)d_in[8];
    const float* b2  = (const float*)d_in[9];

    int       N  = in_sizes[0] / FF;           // 50000
    long long E  = (long long)in_sizes[1] / 2; // 1.6M
    long long EN = E + (long long)N;
    int nb = (N + SCANB - 1) / SCANB;
    float* out = (float*)d_out;

    k_detect<<<1, 32>>>((const long long*)ei, E, N);
    k_zero<<<(N + 255) / 256, 256>>>(N);
    k_hist<<<(unsigned)((EN + 255) / 256), 256>>>(ei, E, N);
    k_scan1<<<nb, SCANB>>>(N);
    k_scan2<<<1, SCANB>>>(nb);
    k_scan3<<<nb, SCANB>>>(N, (int)EN);
    k_scatter<<<(unsigned)((EN + 255) / 256), 256>>>(ei, E, N);
    k_gemm1<<<(N + 63) / 64, 256>>>(x, W1, as1, ad1, N);
    k_agg1<<<(unsigned)(((long long)N * 32 + 255) / 256), 256>>>(b1, N);
    k_gemm2<<<(unsigned)(((long long)N * 32 + 255) / 256), 256>>>(W2, as2, ad2, N);
    k_agg2<<<(unsigned)(((long long)N * 32 + 255) / 256), 256>>>(b2, out, N);
}

// round 7
// speedup vs baseline: 1.9061x; 1.1512x over previous
#include <cuda_runtime.h>
#include <cuda_bf16.h>
#include <cstdint>

// Problem constants (fixed by the dataset)
#define FF  512   // input features
#define HD  64    // H1*D1
#define NH  8     // heads layer 1
#define NC  10    // classes / layer-2 width
#define NMAX 50000
#define EMAX 1700000   // E (1.6M) + N self-loops, rounded up
#define SCANB 256      // scan tile
#define NBMAX ((NMAX + SCANB - 1) / SCANB)

// -------- scratch (static device globals; no allocation allowed) ----------
static __device__ float g_h1  [NMAX*HD];   // layer-1 projected features
static __device__ float g_as1 [NMAX*NH];   // alpha_src layer 1
static __device__ float g_ad1 [NMAX*NH];   // alpha_dst layer 1
static __device__ float g_x2  [NMAX*HD];   // elu(layer-1 output) = layer-2 input
static __device__ float g_h2  [NMAX*NC];   // layer-2 projected features
static __device__ float g_as2 [NMAX];
static __device__ float g_ad2 [NMAX];
static __device__ int   g_cnt [NMAX];      // per-dst degree
static __device__ int   g_off [NMAX+1];    // CSR offsets
static __device__ int   g_cur [NMAX];      // scatter cursors
static __device__ int   g_csr [EMAX];      // CSR src indices (dst-bucketed)
static __device__ int   g_bsum[NBMAX];     // scan block totals -> offsets
static __device__ int   g_is32;            // 1 if edge_index is really int32

// pack two f32 -> bf16x2 (lo16 in low half, hi16 in high half)
__device__ __forceinline__ uint32_t packbf(float lo16, float hi16) {
    uint32_t r;
    asm("cvt.rn.bf16x2.f32 %0, %1, %2;" : "=r"(r) : "f"(hi16), "f"(lo16));
    return r;
}

__device__ __forceinline__ void mma_bf16(float* c, const uint32_t* a, const uint32_t* b) {
    asm volatile(
        "mma.sync.aligned.m16n8k16.row.col.f32.bf16.bf16.f32 "
        "{%0,%1,%2,%3}, {%4,%5,%6,%7}, {%8,%9}, {%0,%1,%2,%3};"
        : "+f"(c[0]), "+f"(c[1]), "+f"(c[2]), "+f"(c[3])
        : "r"(a[0]), "r"(a[1]), "r"(a[2]), "r"(a[3]), "r"(b[0]), "r"(b[1]));
}

// -------- edge dtype sniffer ----------------------------------------------
__global__ void k_detect(const long long* __restrict__ e, long long E, long long N) {
    if (blockIdx.x == 0 && threadIdx.x == 0) {
        int is32 = 0;
        long long cnt = E < 256 ? E : 256;
        for (long long i = 0; i < cnt; i++) {
            long long v = e[i];
            if (v < 0 || v >= N) { is32 = 1; break; }
        }
        g_is32 = is32;
    }
}

// -------- zero degree counters --------------------------------------------
__global__ void k_zero(int N) {
    int i = blockIdx.x * blockDim.x + threadIdx.x;
    if (i < N) g_cnt[i] = 0;
}

// -------- CSR build: histogram --------------------------------------------
__global__ void k_hist(const void* __restrict__ ei, long long E, int N) {
    long long i = (long long)blockIdx.x * blockDim.x + threadIdx.x;
    long long EN = E + (long long)N;
    if (i >= EN) return;
    int d;
    if (i >= E) d = (int)(i - E);
    else if (g_is32) d = ((const int*)ei)[E + i];
    else             d = (int)((const long long*)ei)[E + i];
    atomicAdd(&g_cnt[d], 1);
}

// -------- CSR build: two-level parallel exclusive scan --------------------
__global__ void k_scan1(int N) {
    __shared__ int sh[SCANB];
    int t = threadIdx.x;
    int i = blockIdx.x * SCANB + t;
    int v = (i < N) ? g_cnt[i] : 0;
    sh[t] = v;
    __syncthreads();
    #pragma unroll
    for (int o = 1; o < SCANB; o <<= 1) {
        int u = (t >= o) ? sh[t - o] : 0;
        __syncthreads();
        sh[t] += u;
        __syncthreads();
    }
    if (i < N) g_off[i] = sh[t] - v;
    if (t == SCANB - 1) g_bsum[blockIdx.x] = sh[t];
}

__global__ void k_scan2(int nb) {
    __shared__ int sh[SCANB];
    int t = threadIdx.x;
    int v = (t < nb) ? g_bsum[t] : 0;
    sh[t] = v;
    __syncthreads();
    #pragma unroll
    for (int o = 1; o < SCANB; o <<= 1) {
        int u = (t >= o) ? sh[t - o] : 0;
        __syncthreads();
        sh[t] += u;
        __syncthreads();
    }
    if (t < nb) g_bsum[t] = sh[t] - v;
}

__global__ void k_scan3(int N, int total) {
    int i = blockIdx.x * blockDim.x + threadIdx.x;
    if (i < N) {
        int o = g_off[i] + g_bsum[i / SCANB];
        g_off[i] = o;
        g_cur[i] = o;
    }
    if (i == 0) g_off[N] = total;
}

// -------- CSR build: scatter ----------------------------------------------
__global__ void k_scatter(const void* __restrict__ ei, long long E, int N) {
    long long i = (long long)blockIdx.x * blockDim.x + threadIdx.x;
    long long EN = E + (long long)N;
    if (i >= EN) return;
    int s, d;
    if (i >= E) { s = d = (int)(i - E); }
    else if (g_is32) { const int* p = (const int*)ei; s = p[i]; d = p[E + i]; }
    else { const long long* p = (const long long*)ei; s = (int)p[i]; d = (int)p[E + i]; }
    int pos = atomicAdd(&g_cur[d], 1);
    g_csr[pos] = s;
}

// -------- GEMM1 (tensor cores): h1 = x @ W1, split-bf16, alpha1 fused -----
// C = Xhi*Whi + Xhi*Wlo + Xlo*Whi  (fp32 accum; lo*lo dropped, ~2^-16 rel).
// Block: 128 rows x 64 cols, 256 threads (8 warps, m16 strip each).
// Smem pair-arrays stride 20 words -> conflict-free frag LDS pattern.
__global__ void k_gemm1(const float* __restrict__ x, const float* __restrict__ W,
                        const float* __restrict__ a_src, const float* __restrict__ a_dst,
                        int N) {
    __shared__ uint32_t Ahi[128][20], Alo[128][20];   // [row][k-pair]
    __shared__ uint32_t Bhi[64][20],  Blo[64][20];    // [n][k-pair]
    __shared__ float sA[64], sD[64];

    int tid  = threadIdx.x;
    int lane = tid & 31;
    int warp = tid >> 5;
    int m0   = blockIdx.x * 128;
    int wrow = warp * 16;
    int g = lane >> 2, tg = lane & 3;

    if (tid < 64) { sA[tid] = a_src[tid]; sD[tid] = a_dst[tid]; }

    float c[8][4] = {};   // 8 n-tiles x (c0..c3)

    for (int kk = 0; kk < FF; kk += 32) {
        __syncthreads();   // prev compute done (first iter: covers sA preload)
        // ---- X tile: 128 rows x 32 k, fp32 -> hi/lo bf16 pairs ----
        #pragma unroll
        for (int it = 0; it < 4; it++) {
            int f   = tid + 256 * it;        // 0..1023 float4s
            int row = f >> 3, c4 = f & 7;    // k = c4*4
            float4 v = make_float4(0.f, 0.f, 0.f, 0.f);
            if (m0 + row < N)
                v = *(const float4*)&x[(long long)(m0 + row) * FF + kk + c4 * 4];
            float hx = __bfloat162float(__float2bfloat16(v.x));
            float hy = __bfloat162float(__float2bfloat16(v.y));
            float hz = __bfloat162float(__float2bfloat16(v.z));
            float hw = __bfloat162float(__float2bfloat16(v.w));
            Ahi[row][c4*2+0] = packbf(hx, hy);
            Ahi[row][c4*2+1] = packbf(hz, hw);
            Alo[row][c4*2+0] = packbf(v.x - hx, v.y - hy);
            Alo[row][c4*2+1] = packbf(v.z - hz, v.w - hw);
        }
        // ---- W tile: 32 k x 64 n -> [n][k-pair] ----
        {
            int j = tid >> 4, n4 = tid & 15;     // k-pair j (0..15), n base n4*4
            float4 w0 = *(const float4*)&W[(kk + 2*j)     * 64 + n4 * 4];
            float4 w1 = *(const float4*)&W[(kk + 2*j + 1) * 64 + n4 * 4];
            const float e0[4] = {w0.x, w0.y, w0.z, w0.w};
            const float e1[4] = {w1.x, w1.y, w1.z, w1.w};
            #pragma unroll
            for (int i = 0; i < 4; i++) {
                float h0 = __bfloat162float(__float2bfloat16(e0[i]));
                float h1 = __bfloat162float(__float2bfloat16(e1[i]));
                Bhi[n4*4 + i][j] = packbf(h0, h1);
                Blo[n4*4 + i][j] = packbf(e0[i] - h0, e1[i] - h1);
            }
        }
        __syncthreads();
        // ---- compute: two k16 sub-steps ----
        #pragma unroll
        for (int sub = 0; sub < 2; sub++) {
            int po = sub * 8;
            uint32_t ah[4], al[4];
            ah[0] = Ahi[wrow + g    ][po + tg];
            ah[1] = Ahi[wrow + g + 8][po + tg];
            ah[2] = Ahi[wrow + g    ][po + tg + 4];
            ah[3] = Ahi[wrow + g + 8][po + tg + 4];
            al[0] = Alo[wrow + g    ][po + tg];
            al[1] = Alo[wrow + g + 8][po + tg];
            al[2] = Alo[wrow + g    ][po + tg + 4];
            al[3] = Alo[wrow + g + 8][po + tg + 4];
            #pragma unroll
            for (int t = 0; t < 8; t++) {
                uint32_t bh[2], bl[2];
                bh[0] = Bhi[t*8 + g][po + tg];
                bh[1] = Bhi[t*8 + g][po + tg + 4];
                bl[0] = Blo[t*8 + g][po + tg];
                bl[1] = Blo[t*8 + g][po + tg + 4];
                mma_bf16(c[t], ah, bh);
                mma_bf16(c[t], ah, bl);
                mma_bf16(c[t], al, bh);
            }
        }
    }

    // ---- epilogue: store h1 + fused alpha projections ----
    int row0 = m0 + wrow + g;
    int row1 = row0 + 8;
    #pragma unroll
    for (int t = 0; t < 8; t++) {
        if (row0 < N)
            *(float2*)&g_h1[row0 * 64 + t*8 + tg*2] = make_float2(c[t][0], c[t][1]);
        if (row1 < N)
            *(float2*)&g_h1[row1 * 64 + t*8 + tg*2] = make_float2(c[t][2], c[t][3]);
        // alpha partials: head t covers cols t*8..t*8+7; lane tg has 2 cols
        float as = sA[t*8 + tg*2], as2v = sA[t*8 + tg*2 + 1];
        float ad = sD[t*8 + tg*2], ad2v = sD[t*8 + tg*2 + 1];
        float s0 = c[t][0]*as + c[t][1]*as2v;   // row0
        float d0 = c[t][0]*ad + c[t][1]*ad2v;
        float s1 = c[t][2]*as + c[t][3]*as2v;   // row1
        float d1 = c[t][2]*ad + c[t][3]*ad2v;
        #pragma unroll
        for (int o = 1; o <= 2; o <<= 1) {
            s0 += __shfl_xor_sync(0xffffffffu, s0, o);
            d0 += __shfl_xor_sync(0xffffffffu, d0, o);
            s1 += __shfl_xor_sync(0xffffffffu, s1, o);
            d1 += __shfl_xor_sync(0xffffffffu, d1, o);
        }
        if (tg == 0) {
            if (row0 < N) { g_as1[row0 * 8 + t] = s0; g_ad1[row0 * 8 + t] = d0; }
            if (row1 < N) { g_as1[row1 * 8 + t] = s1; g_ad1[row1 * 8 + t] = d1; }
        }
    }
}

// -------- aggregation layer 1 (warp per dst, CSR, no atomics) -------------
// float2 lane layout: lane covers features 2*lane, 2*lane+1 (same head,
// head = lane>>2). One LDG.64 + one shuffle per edge per lane.
__global__ void k_agg1(const float* __restrict__ b1, int N) {
    int d = (blockIdx.x * blockDim.x + threadIdx.x) >> 5;
    int lane = threadIdx.x & 31;
    if (d >= N) return;
    int beg = g_off[d], end = g_off[d + 1];
    float ad_l = (lane < NH) ? g_ad1[d * NH + lane] : 0.f;
    float accx = 0.f, accy = 0.f, den = 0.f;
    for (int i = beg; i < end; i++) {
        int s = g_csr[i];
        float w = 0.f;
        if (lane < NH) {
            float e = g_as1[s * NH + lane] + ad_l;
            e = e > 0.f ? e : 0.2f * e;          // LeakyReLU(0.2)
            w = __expf(e);
            den += w;
        }
        float wl = __shfl_sync(0xffffffffu, w, lane >> 2);   // head of 2*lane
        float2 hv = *(const float2*)&g_h1[s * 64 + lane * 2];
        accx += wl * hv.x;
        accy += wl * hv.y;
    }
    float denl = __shfl_sync(0xffffffffu, den, lane >> 2);
    float v0 = accx / denl + b1[2 * lane];
    float v1 = accy / denl + b1[2 * lane + 1];
    v0 = v0 > 0.f ? v0 : expm1f(v0);         // ELU
    v1 = v1 > 0.f ? v1 : expm1f(v1);
    *(float2*)&g_x2[d * 64 + 2 * lane] = make_float2(v0, v1);
}

// -------- GEMM2 + alpha projections layer 2 (warp per node) ---------------
__global__ void k_gemm2(const float* __restrict__ W2,
                        const float* __restrict__ a_src2,
                        const float* __restrict__ a_dst2, int N) {
    int wid = (blockIdx.x * blockDim.x + threadIdx.x) >> 5;
    int lane = threadIdx.x & 31;
    if (wid >= N) return;
    float v0 = g_x2[wid * 64 + lane];
    float v1 = g_x2[wid * 64 + 32 + lane];
    float asum = 0.f, adsum = 0.f;
    #pragma unroll
    for (int c = 0; c < NC; c++) {
        float s = v0 * W2[lane * NC + c] + v1 * W2[(lane + 32) * NC + c];
        #pragma unroll
        for (int o = 16; o; o >>= 1) s += __shfl_down_sync(0xffffffffu, s, o);
        if (lane == 0) {
            g_h2[wid * NC + c] = s;
            asum  += s * a_src2[c];
            adsum += s * a_dst2[c];
        }
    }
    if (lane == 0) { g_as2[wid] = asum; g_ad2[wid] = adsum; }
}

// -------- aggregation layer 2 (warp per dst, lanes over edges) ------------
__global__ void k_agg2(const float* __restrict__ b2, float* __restrict__ out, int N) {
    int d = (blockIdx.x * blockDim.x + threadIdx.x) >> 5;
    int lane = threadIdx.x & 31;
    if (d >= N) return;
    int beg = g_off[d], end = g_off[d + 1];
    float ad_d = g_ad2[d];
    float acc[NC] = {};
    float den = 0.f;
    for (int i = beg + lane; i < end; i += 32) {
        int s = g_csr[i];
        float e = g_as2[s] + ad_d;
        e = e > 0.f ? e : 0.2f * e;
        float w = __expf(e);
        den += w;
        const float* hp = &g_h2[s * NC];
        #pragma unroll
        for (int c = 0; c < NC; c++) acc[c] += w * hp[c];
    }
    #pragma unroll
    for (int o = 16; o; o >>= 1) {
        den += __shfl_down_sync(0xffffffffu, den, o);
        #pragma unroll
        for (int c = 0; c < NC; c++)
            acc[c] += __shfl_down_sync(0xffffffffu, acc[c], o);
    }
    if (lane == 0) {
        float inv = 1.f / den;
        float v[NC], m = -1e30f;
        #pragma unroll
        for (int c = 0; c < NC; c++) {
            v[c] = acc[c] * inv + b2[c];
            m = fmaxf(m, v[c]);
        }
        float ssum = 0.f;
        #pragma unroll
        for (int c = 0; c < NC; c++) ssum += __expf(v[c] - m);
        float l = __logf(ssum);
        #pragma unroll
        for (int c = 0; c < NC; c++) out[d * NC + c] = v[c] - m - l;
    }
}

// ---------------------------------------------------------------------------
extern "C" void kernel_launch(void* const* d_in, const int* in_sizes, int n_in,
                              void* d_out, int out_size) {
    const float* x   = (const float*)d_in[0];
    const void*  ei  = d_in[1];
    const float* W1  = (const float*)d_in[2];
    const float* as1 = (const float*)d_in[3];
    const float* ad1 = (const float*)d_in[4];
    const float* b1  = (const float*)d_in[5];
    const float* W2  = (const float*)d_in[6];
    const float* as2 = (const float*)d_in[7];
    const float* ad2 = (const float*)d_in[8];
    const float* b2  = (const float*)d_in[9];

    int       N  = in_sizes[0] / FF;           // 50000
    long long E  = (long long)in_sizes[1] / 2; // 1.6M
    long long EN = E + (long long)N;
    int nb = (N + SCANB - 1) / SCANB;
    float* out = (float*)d_out;

    k_detect<<<1, 32>>>((const long long*)ei, E, N);
    k_zero<<<(N + 255) / 256, 256>>>(N);
    k_hist<<<(unsigned)((EN + 255) / 256), 256>>>(ei, E, N);
    k_scan1<<<nb, SCANB>>>(N);
    k_scan2<<<1, SCANB>>>(nb);
    k_scan3<<<nb, SCANB>>>(N, (int)EN);
    k_scatter<<<(unsigned)((EN + 255) / 256), 256>>>(ei, E, N);
    k_gemm1<<<(N + 127) / 128, 256>>>(x, W1, as1, ad1, N);
    k_agg1<<<(unsigned)(((long long)N * 32 + 255) / 256), 256>>>(b1, N);
    k_gemm2<<<(unsigned)(((long long)N * 32 + 255) / 256), 256>>>(W2, as2, ad2, N);
    k_agg2<<<(unsigned)(((long long)N * 32 + 255) / 256), 256>>>(b2, out, N);
}

// round 8
// speedup vs baseline: 2.0932x; 1.0982x over previous
#include <cuda_runtime.h>
#include <cuda_bf16.h>
#include <cstdint>

// Problem constants (fixed by the dataset)
#define FF  512   // input features
#define HD  64    // H1*D1
#define NH  8     // heads layer 1
#define NC  10    // classes / layer-2 width
#define NMAX 50000
#define EMAX 1700000   // E (1.6M) + N self-loops, rounded up
#define SCANB 256      // scan tile
#define NBMAX ((NMAX + SCANB - 1) / SCANB)

// -------- scratch (static device globals; no allocation allowed) ----------
static __device__ float g_h1  [NMAX*HD];   // layer-1 projected features
static __device__ float g_as1 [NMAX*NH];   // alpha_src layer 1
static __device__ float g_ad1 [NMAX*NH];   // alpha_dst layer 1
static __device__ float g_x2  [NMAX*HD];   // elu(layer-1 output) = layer-2 input
static __device__ float g_h2  [NMAX*NC];   // layer-2 projected features
static __device__ float g_as2 [NMAX];
static __device__ float g_ad2 [NMAX];
static __device__ int   g_cnt [NMAX];      // per-dst degree
static __device__ int   g_off [NMAX+1];    // CSR offsets
static __device__ int   g_cur [NMAX];      // scatter cursors
static __device__ int   g_csr [EMAX];      // CSR src indices (dst-bucketed)
static __device__ int   g_bsum[NBMAX];     // scan block totals -> offsets
static __device__ int   g_is32;            // 1 if edge_index is really int32

// pack two f32 -> bf16x2 (lo16 in low half, hi16 in high half)
__device__ __forceinline__ uint32_t packbf(float lo16, float hi16) {
    uint32_t r;
    asm("cvt.rn.bf16x2.f32 %0, %1, %2;" : "=r"(r) : "f"(hi16), "f"(lo16));
    return r;
}

__device__ __forceinline__ void mma_bf16(float* c, const uint32_t* a, const uint32_t* b) {
    asm volatile(
        "mma.sync.aligned.m16n8k16.row.col.f32.bf16.bf16.f32 "
        "{%0,%1,%2,%3}, {%4,%5,%6,%7}, {%8,%9}, {%0,%1,%2,%3};"
        : "+f"(c[0]), "+f"(c[1]), "+f"(c[2]), "+f"(c[3])
        : "r"(a[0]), "r"(a[1]), "r"(a[2]), "r"(a[3]), "r"(b[0]), "r"(b[1]));
}

// -------- edge dtype sniffer ----------------------------------------------
__global__ void k_detect(const long long* __restrict__ e, long long E, long long N) {
    if (blockIdx.x == 0 && threadIdx.x == 0) {
        int is32 = 0;
        long long cnt = E < 256 ? E : 256;
        for (long long i = 0; i < cnt; i++) {
            long long v = e[i];
            if (v < 0 || v >= N) { is32 = 1; break; }
        }
        g_is32 = is32;
    }
}

// -------- zero degree counters --------------------------------------------
__global__ void k_zero(int N) {
    int i = blockIdx.x * blockDim.x + threadIdx.x;
    if (i < N) g_cnt[i] = 0;
}

// -------- CSR build: histogram --------------------------------------------
__global__ void k_hist(const void* __restrict__ ei, long long E, int N) {
    long long i = (long long)blockIdx.x * blockDim.x + threadIdx.x;
    long long EN = E + (long long)N;
    if (i >= EN) return;
    int d;
    if (i >= E) d = (int)(i - E);
    else if (g_is32) d = ((const int*)ei)[E + i];
    else             d = (int)((const long long*)ei)[E + i];
    atomicAdd(&g_cnt[d], 1);
}

// -------- CSR build: two-level parallel exclusive scan --------------------
__global__ void k_scan1(int N) {
    __shared__ int sh[SCANB];
    int t = threadIdx.x;
    int i = blockIdx.x * SCANB + t;
    int v = (i < N) ? g_cnt[i] : 0;
    sh[t] = v;
    __syncthreads();
    #pragma unroll
    for (int o = 1; o < SCANB; o <<= 1) {
        int u = (t >= o) ? sh[t - o] : 0;
        __syncthreads();
        sh[t] += u;
        __syncthreads();
    }
    if (i < N) g_off[i] = sh[t] - v;
    if (t == SCANB - 1) g_bsum[blockIdx.x] = sh[t];
}

__global__ void k_scan2(int nb) {
    __shared__ int sh[SCANB];
    int t = threadIdx.x;
    int v = (t < nb) ? g_bsum[t] : 0;
    sh[t] = v;
    __syncthreads();
    #pragma unroll
    for (int o = 1; o < SCANB; o <<= 1) {
        int u = (t >= o) ? sh[t - o] : 0;
        __syncthreads();
        sh[t] += u;
        __syncthreads();
    }
    if (t < nb) g_bsum[t] = sh[t] - v;
}

__global__ void k_scan3(int N, int total) {
    int i = blockIdx.x * blockDim.x + threadIdx.x;
    if (i < N) {
        int o = g_off[i] + g_bsum[i / SCANB];
        g_off[i] = o;
        g_cur[i] = o;
    }
    if (i == 0) g_off[N] = total;
}

// -------- CSR build: scatter ----------------------------------------------
__global__ void k_scatter(const void* __restrict__ ei, long long E, int N) {
    long long i = (long long)blockIdx.x * blockDim.x + threadIdx.x;
    long long EN = E + (long long)N;
    if (i >= EN) return;
    int s, d;
    if (i >= E) { s = d = (int)(i - E); }
    else if (g_is32) { const int* p = (const int*)ei; s = p[i]; d = p[E + i]; }
    else { const long long* p = (const long long*)ei; s = (int)p[i]; d = (int)p[E + i]; }
    int pos = atomicAdd(&g_cur[d], 1);
    g_csr[pos] = s;
}

// -------- GEMM1 (tensor cores): h1 = x @ W1, split-bf16, alpha1 fused -----
// C = Xhi*Whi + Xhi*Wlo + Xlo*Whi  (fp32 accum; lo*lo dropped, ~2^-16 rel).
__global__ void k_gemm1(const float* __restrict__ x, const float* __restrict__ W,
                        const float* __restrict__ a_src, const float* __restrict__ a_dst,
                        int N) {
    __shared__ uint32_t Ahi[128][20], Alo[128][20];   // [row][k-pair]
    __shared__ uint32_t Bhi[64][20],  Blo[64][20];    // [n][k-pair]
    __shared__ float sA[64], sD[64];

    int tid  = threadIdx.x;
    int lane = tid & 31;
    int warp = tid >> 5;
    int m0   = blockIdx.x * 128;
    int wrow = warp * 16;
    int g = lane >> 2, tg = lane & 3;

    if (tid < 64) { sA[tid] = a_src[tid]; sD[tid] = a_dst[tid]; }

    float c[8][4] = {};   // 8 n-tiles x (c0..c3)

    for (int kk = 0; kk < FF; kk += 32) {
        __syncthreads();   // prev compute done (first iter: covers sA preload)
        // ---- X tile: 128 rows x 32 k, fp32 -> hi/lo bf16 pairs ----
        #pragma unroll
        for (int it = 0; it < 4; it++) {
            int f   = tid + 256 * it;        // 0..1023 float4s
            int row = f >> 3, c4 = f & 7;    // k = c4*4
            float4 v = make_float4(0.f, 0.f, 0.f, 0.f);
            if (m0 + row < N)
                v = *(const float4*)&x[(long long)(m0 + row) * FF + kk + c4 * 4];
            float hx = __bfloat162float(__float2bfloat16(v.x));
            float hy = __bfloat162float(__float2bfloat16(v.y));
            float hz = __bfloat162float(__float2bfloat16(v.z));
            float hw = __bfloat162float(__float2bfloat16(v.w));
            Ahi[row][c4*2+0] = packbf(hx, hy);
            Ahi[row][c4*2+1] = packbf(hz, hw);
            Alo[row][c4*2+0] = packbf(v.x - hx, v.y - hy);
            Alo[row][c4*2+1] = packbf(v.z - hz, v.w - hw);
        }
        // ---- W tile: 32 k x 64 n -> [n][k-pair] ----
        {
            int j = tid >> 4, n4 = tid & 15;     // k-pair j (0..15), n base n4*4
            float4 w0 = *(const float4*)&W[(kk + 2*j)     * 64 + n4 * 4];
            float4 w1 = *(const float4*)&W[(kk + 2*j + 1) * 64 + n4 * 4];
            const float e0[4] = {w0.x, w0.y, w0.z, w0.w};
            const float e1[4] = {w1.x, w1.y, w1.z, w1.w};
            #pragma unroll
            for (int i = 0; i < 4; i++) {
                float h0 = __bfloat162float(__float2bfloat16(e0[i]));
                float h1 = __bfloat162float(__float2bfloat16(e1[i]));
                Bhi[n4*4 + i][j] = packbf(h0, h1);
                Blo[n4*4 + i][j] = packbf(e0[i] - h0, e1[i] - h1);
            }
        }
        __syncthreads();
        // ---- compute: two k16 sub-steps ----
        #pragma unroll
        for (int sub = 0; sub < 2; sub++) {
            int po = sub * 8;
            uint32_t ah[4], al[4];
            ah[0] = Ahi[wrow + g    ][po + tg];
            ah[1] = Ahi[wrow + g + 8][po + tg];
            ah[2] = Ahi[wrow + g    ][po + tg + 4];
            ah[3] = Ahi[wrow + g + 8][po + tg + 4];
            al[0] = Alo[wrow + g    ][po + tg];
            al[1] = Alo[wrow + g + 8][po + tg];
            al[2] = Alo[wrow + g    ][po + tg + 4];
            al[3] = Alo[wrow + g + 8][po + tg + 4];
            #pragma unroll
            for (int t = 0; t < 8; t++) {
                uint32_t bh[2], bl[2];
                bh[0] = Bhi[t*8 + g][po + tg];
                bh[1] = Bhi[t*8 + g][po + tg + 4];
                bl[0] = Blo[t*8 + g][po + tg];
                bl[1] = Blo[t*8 + g][po + tg + 4];
                mma_bf16(c[t], ah, bh);
                mma_bf16(c[t], ah, bl);
                mma_bf16(c[t], al, bh);
            }
        }
    }

    // ---- epilogue: store h1 + fused alpha projections ----
    int row0 = m0 + wrow + g;
    int row1 = row0 + 8;
    #pragma unroll
    for (int t = 0; t < 8; t++) {
        if (row0 < N)
            *(float2*)&g_h1[row0 * 64 + t*8 + tg*2] = make_float2(c[t][0], c[t][1]);
        if (row1 < N)
            *(float2*)&g_h1[row1 * 64 + t*8 + tg*2] = make_float2(c[t][2], c[t][3]);
        float as = sA[t*8 + tg*2], as2v = sA[t*8 + tg*2 + 1];
        float ad = sD[t*8 + tg*2], ad2v = sD[t*8 + tg*2 + 1];
        float s0 = c[t][0]*as + c[t][1]*as2v;   // row0
        float d0 = c[t][0]*ad + c[t][1]*ad2v;
        float s1 = c[t][2]*as + c[t][3]*as2v;   // row1
        float d1 = c[t][2]*ad + c[t][3]*ad2v;
        #pragma unroll
        for (int o = 1; o <= 2; o <<= 1) {
            s0 += __shfl_xor_sync(0xffffffffu, s0, o);
            d0 += __shfl_xor_sync(0xffffffffu, d0, o);
            s1 += __shfl_xor_sync(0xffffffffu, s1, o);
            d1 += __shfl_xor_sync(0xffffffffu, d1, o);
        }
        if (tg == 0) {
            if (row0 < N) { g_as1[row0 * 8 + t] = s0; g_ad1[row0 * 8 + t] = d0; }
            if (row1 < N) { g_as1[row1 * 8 + t] = s1; g_ad1[row1 * 8 + t] = d1; }
        }
    }
}

// -------- aggregation layer 1 (warp per dst, CSR, no atomics) -------------
__global__ void k_agg1(const float* __restrict__ b1, int N) {
    int d = (blockIdx.x * blockDim.x + threadIdx.x) >> 5;
    int lane = threadIdx.x & 31;
    if (d >= N) return;
    int beg = g_off[d], end = g_off[d + 1];
    float ad_l = (lane < NH) ? g_ad1[d * NH + lane] : 0.f;
    float accx = 0.f, accy = 0.f, den = 0.f;
    for (int i = beg; i < end; i++) {
        int s = g_csr[i];
        float w = 0.f;
        if (lane < NH) {
            float e = g_as1[s * NH + lane] + ad_l;
            e = e > 0.f ? e : 0.2f * e;          // LeakyReLU(0.2)
            w = __expf(e);
            den += w;
        }
        float wl = __shfl_sync(0xffffffffu, w, lane >> 2);   // head of 2*lane
        float2 hv = *(const float2*)&g_h1[s * 64 + lane * 2];
        accx += wl * hv.x;
        accy += wl * hv.y;
    }
    float denl = __shfl_sync(0xffffffffu, den, lane >> 2);
    float v0 = accx / denl + b1[2 * lane];
    float v1 = accy / denl + b1[2 * lane + 1];
    v0 = v0 > 0.f ? v0 : expm1f(v0);         // ELU
    v1 = v1 > 0.f ? v1 : expm1f(v1);
    *(float2*)&g_x2[d * 64 + 2 * lane] = make_float2(v0, v1);
}

// -------- GEMM2 + alpha projections layer 2 (warp per node) ---------------
__global__ void k_gemm2(const float* __restrict__ W2,
                        const float* __restrict__ a_src2,
                        const float* __restrict__ a_dst2, int N) {
    int wid = (blockIdx.x * blockDim.x + threadIdx.x) >> 5;
    int lane = threadIdx.x & 31;
    if (wid >= N) return;
    float v0 = g_x2[wid * 64 + lane];
    float v1 = g_x2[wid * 64 + 32 + lane];
    float asum = 0.f, adsum = 0.f;
    #pragma unroll
    for (int c = 0; c < NC; c++) {
        float s = v0 * W2[lane * NC + c] + v1 * W2[(lane + 32) * NC + c];
        #pragma unroll
        for (int o = 16; o; o >>= 1) s += __shfl_down_sync(0xffffffffu, s, o);
        if (lane == 0) {
            g_h2[wid * NC + c] = s;
            asum  += s * a_src2[c];
            adsum += s * a_dst2[c];
        }
    }
    if (lane == 0) { g_as2[wid] = asum; g_ad2[wid] = adsum; }
}

// -------- aggregation layer 2 (warp per dst, lanes over edges) ------------
__global__ void k_agg2(const float* __restrict__ b2, float* __restrict__ out, int N) {
    int d = (blockIdx.x * blockDim.x + threadIdx.x) >> 5;
    int lane = threadIdx.x & 31;
    if (d >= N) return;
    int beg = g_off[d], end = g_off[d + 1];
    float ad_d = g_ad2[d];
    float acc[NC] = {};
    float den = 0.f;
    for (int i = beg + lane; i < end; i += 32) {
        int s = g_csr[i];
        float e = g_as2[s] + ad_d;
        e = e > 0.f ? e : 0.2f * e;
        float w = __expf(e);
        den += w;
        const float* hp = &g_h2[s * NC];
        #pragma unroll
        for (int c = 0; c < NC; c++) acc[c] += w * hp[c];
    }
    #pragma unroll
    for (int o = 16; o; o >>= 1) {
        den += __shfl_down_sync(0xffffffffu, den, o);
        #pragma unroll
        for (int c = 0; c < NC; c++)
            acc[c] += __shfl_down_sync(0xffffffffu, acc[c], o);
    }
    if (lane == 0) {
        float inv = 1.f / den;
        float v[NC], m = -1e30f;
        #pragma unroll
        for (int c = 0; c < NC; c++) {
            v[c] = acc[c] * inv + b2[c];
            m = fmaxf(m, v[c]);
        }
        float ssum = 0.f;
        #pragma unroll
        for (int c = 0; c < NC; c++) ssum += __expf(v[c] - m);
        float l = __logf(ssum);
        #pragma unroll
        for (int c = 0; c < NC; c++) out[d * NC + c] = v[c] - m - l;
    }
}

// ---------------------------------------------------------------------------
// Fork/join launcher: the CSR-build chain (edge_index only) runs on a side
// stream concurrently with k_gemm1 (x/W1 only); they join before k_agg1.
// Capture-legal: event record on the capture stream + StreamWaitEvent forks
// the side stream into the same capture graph; the join wait merges it back.
extern "C" void kernel_launch(void* const* d_in, const int* in_sizes, int n_in,
                              void* d_out, int out_size) {
    const float* x   = (const float*)d_in[0];
    const void*  ei  = d_in[1];
    const float* W1  = (const float*)d_in[2];
    const float* as1 = (const float*)d_in[3];
    const float* ad1 = (const float*)d_in[4];
    const float* b1  = (const float*)d_in[5];
    const float* W2  = (const float*)d_in[6];
    const float* as2 = (const float*)d_in[7];
    const float* ad2 = (const float*)d_in[8];
    const float* b2  = (const float*)d_in[9];

    int       N  = in_sizes[0] / FF;           // 50000
    long long E  = (long long)in_sizes[1] / 2; // 1.6M
    long long EN = E + (long long)N;
    int nb = (N + SCANB - 1) / SCANB;
    float* out = (float*)d_out;

    cudaStream_t s1 = 0;
    cudaEvent_t ev0 = 0, ev1 = 0;
    bool forked =
        cudaStreamCreateWithFlags(&s1, cudaStreamNonBlocking) == cudaSuccess &&
        cudaEventCreateWithFlags(&ev0, cudaEventDisableTiming) == cudaSuccess &&
        cudaEventCreateWithFlags(&ev1, cudaEventDisableTiming) == cudaSuccess;

    if (forked) forked = cudaEventRecord(ev0, 0) == cudaSuccess &&
                         cudaStreamWaitEvent(s1, ev0, 0) == cudaSuccess;

    cudaStream_t cs = forked ? s1 : 0;   // CSR chain stream (falls back serial)

    // ---- branch A: CSR build (depends only on edge_index) ----
    k_detect<<<1, 32, 0, cs>>>((const long long*)ei, E, N);
    k_zero<<<(N + 255) / 256, 256, 0, cs>>>(N);
    k_hist<<<(unsigned)((EN + 255) / 256), 256, 0, cs>>>(ei, E, N);
    k_scan1<<<nb, SCANB, 0, cs>>>(N);
    k_scan2<<<1, SCANB, 0, cs>>>(nb);
    k_scan3<<<nb, SCANB, 0, cs>>>(N, (int)EN);
    k_scatter<<<(unsigned)((EN + 255) / 256), 256, 0, cs>>>(ei, E, N);
    if (forked) forked = cudaEventRecord(ev1, s1) == cudaSuccess;

    // ---- branch B: projection GEMM (depends only on x, W1) ----
    k_gemm1<<<(N + 127) / 128, 256>>>(x, W1, as1, ad1, N);

    // ---- join, then the dependent tail ----
    if (forked) cudaStreamWaitEvent(0, ev1, 0);

    k_agg1<<<(unsigned)(((long long)N * 32 + 255) / 256), 256>>>(b1, N);
    k_gemm2<<<(unsigned)(((long long)N * 32 + 255) / 256), 256>>>(W2, as2, ad2, N);
    k_agg2<<<(unsigned)(((long long)N * 32 + 255) / 256), 256>>>(b2, out, N);
    // Streams/events are intentionally not destroyed here: destroying a
    // forked stream mid-capture is illegal, and kernel_launch is invoked only
    // O(1) times by the harness (host-side handles only, no device memory).
}

// round 9
// speedup vs baseline: 2.0965x; 1.0016x over previous
#include <cuda_runtime.h>
#include <cuda_bf16.h>
#include <cstdint>

// Problem constants (fixed by the dataset)
#define FF  512   // input features
#define HD  64    // H1*D1
#define NH  8     // heads layer 1
#define NC  10    // classes / layer-2 width
#define NMAX 50000
#define EMAX 1700000   // E (1.6M) + N self-loops, rounded up
#define SCANB 256      // scan tile
#define NBMAX ((NMAX + SCANB - 1) / SCANB)

// -------- scratch (static device globals; no allocation allowed) ----------
static __device__ float g_h1  [NMAX*HD];   // layer-1 projected features
static __device__ float g_as1 [NMAX*NH];   // alpha_src layer 1
static __device__ float g_ad1 [NMAX*NH];   // alpha_dst layer 1
static __device__ float g_x2  [NMAX*HD];   // elu(layer-1 output) = layer-2 input
static __device__ float g_h2  [NMAX*NC];   // layer-2 projected features
static __device__ float g_as2 [NMAX];
static __device__ float g_ad2 [NMAX];
static __device__ int   g_cnt [NMAX];      // per-dst degree
static __device__ int   g_off [NMAX+1];    // CSR offsets
static __device__ int   g_cur [NMAX];      // scatter cursors
static __device__ int   g_csr [EMAX];      // CSR src indices (dst-bucketed)
static __device__ int   g_bsum[NBMAX];     // scan block totals -> offsets
static __device__ int   g_is32;            // 1 if edge_index is really int32

// pack two f32 -> bf16x2 (lo16 in low half, hi16 in high half)
__device__ __forceinline__ uint32_t packbf(float lo16, float hi16) {
    uint32_t r;
    asm("cvt.rn.bf16x2.f32 %0, %1, %2;" : "=r"(r) : "f"(hi16), "f"(lo16));
    return r;
}

__device__ __forceinline__ void mma_bf16(float* c, const uint32_t* a, const uint32_t* b) {
    asm volatile(
        "mma.sync.aligned.m16n8k16.row.col.f32.bf16.bf16.f32 "
        "{%0,%1,%2,%3}, {%4,%5,%6,%7}, {%8,%9}, {%0,%1,%2,%3};"
        : "+f"(c[0]), "+f"(c[1]), "+f"(c[2]), "+f"(c[3])
        : "r"(a[0]), "r"(a[1]), "r"(a[2]), "r"(a[3]), "r"(b[0]), "r"(b[1]));
}

// -------- edge dtype sniffer ----------------------------------------------
__global__ void k_detect(const long long* __restrict__ e, long long E, long long N) {
    if (blockIdx.x == 0 && threadIdx.x == 0) {
        int is32 = 0;
        long long cnt = E < 256 ? E : 256;
        for (long long i = 0; i < cnt; i++) {
            long long v = e[i];
            if (v < 0 || v >= N) { is32 = 1; break; }
        }
        g_is32 = is32;
    }
}

// -------- zero degree counters --------------------------------------------
__global__ void k_zero(int N) {
    int i = blockIdx.x * blockDim.x + threadIdx.x;
    if (i < N) g_cnt[i] = 0;
}

// -------- CSR build: histogram --------------------------------------------
__global__ void k_hist(const void* __restrict__ ei, long long E, int N) {
    long long i = (long long)blockIdx.x * blockDim.x + threadIdx.x;
    long long EN = E + (long long)N;
    if (i >= EN) return;
    int d;
    if (i >= E) d = (int)(i - E);
    else if (g_is32) d = ((const int*)ei)[E + i];
    else             d = (int)((const long long*)ei)[E + i];
    atomicAdd(&g_cnt[d], 1);
}

// -------- CSR build: two-level parallel exclusive scan --------------------
__global__ void k_scan1(int N) {
    __shared__ int sh[SCANB];
    int t = threadIdx.x;
    int i = blockIdx.x * SCANB + t;
    int v = (i < N) ? g_cnt[i] : 0;
    sh[t] = v;
    __syncthreads();
    #pragma unroll
    for (int o = 1; o < SCANB; o <<= 1) {
        int u = (t >= o) ? sh[t - o] : 0;
        __syncthreads();
        sh[t] += u;
        __syncthreads();
    }
    if (i < N) g_off[i] = sh[t] - v;
    if (t == SCANB - 1) g_bsum[blockIdx.x] = sh[t];
}

__global__ void k_scan2(int nb) {
    __shared__ int sh[SCANB];
    int t = threadIdx.x;
    int v = (t < nb) ? g_bsum[t] : 0;
    sh[t] = v;
    __syncthreads();
    #pragma unroll
    for (int o = 1; o < SCANB; o <<= 1) {
        int u = (t >= o) ? sh[t - o] : 0;
        __syncthreads();
        sh[t] += u;
        __syncthreads();
    }
    if (t < nb) g_bsum[t] = sh[t] - v;
}

__global__ void k_scan3(int N, int total) {
    int i = blockIdx.x * blockDim.x + threadIdx.x;
    if (i < N) {
        int o = g_off[i] + g_bsum[i / SCANB];
        g_off[i] = o;
        g_cur[i] = o;
    }
    if (i == 0) g_off[N] = total;
}

// -------- CSR build: scatter ----------------------------------------------
__global__ void k_scatter(const void* __restrict__ ei, long long E, int N) {
    long long i = (long long)blockIdx.x * blockDim.x + threadIdx.x;
    long long EN = E + (long long)N;
    if (i >= EN) return;
    int s, d;
    if (i >= E) { s = d = (int)(i - E); }
    else if (g_is32) { const int* p = (const int*)ei; s = p[i]; d = p[E + i]; }
    else { const long long* p = (const long long*)ei; s = (int)p[i]; d = (int)p[E + i]; }
    int pos = atomicAdd(&g_cur[d], 1);
    g_csr[pos] = s;
}

// -------- GEMM1 (tensor cores): h1 = x @ W1, split-bf16, alpha1 fused -----
// C = Xhi*Whi + Xhi*Wlo + Xlo*Whi  (fp32 accum; lo*lo dropped, ~2^-16 rel).
__global__ void k_gemm1(const float* __restrict__ x, const float* __restrict__ W,
                        const float* __restrict__ a_src, const float* __restrict__ a_dst,
                        int N) {
    __shared__ uint32_t Ahi[128][20], Alo[128][20];   // [row][k-pair]
    __shared__ uint32_t Bhi[64][20],  Blo[64][20];    // [n][k-pair]
    __shared__ float sA[64], sD[64];

    int tid  = threadIdx.x;
    int lane = tid & 31;
    int warp = tid >> 5;
    int m0   = blockIdx.x * 128;
    int wrow = warp * 16;
    int g = lane >> 2, tg = lane & 3;

    if (tid < 64) { sA[tid] = a_src[tid]; sD[tid] = a_dst[tid]; }

    float c[8][4] = {};   // 8 n-tiles x (c0..c3)

    for (int kk = 0; kk < FF; kk += 32) {
        __syncthreads();   // prev compute done (first iter: covers sA preload)
        // ---- X tile: 128 rows x 32 k, fp32 -> hi/lo bf16 pairs ----
        #pragma unroll
        for (int it = 0; it < 4; it++) {
            int f   = tid + 256 * it;        // 0..1023 float4s
            int row = f >> 3, c4 = f & 7;    // k = c4*4
            float4 v = make_float4(0.f, 0.f, 0.f, 0.f);
            if (m0 + row < N)
                v = *(const float4*)&x[(long long)(m0 + row) * FF + kk + c4 * 4];
            float hx = __bfloat162float(__float2bfloat16(v.x));
            float hy = __bfloat162float(__float2bfloat16(v.y));
            float hz = __bfloat162float(__float2bfloat16(v.z));
            float hw = __bfloat162float(__float2bfloat16(v.w));
            Ahi[row][c4*2+0] = packbf(hx, hy);
            Ahi[row][c4*2+1] = packbf(hz, hw);
            Alo[row][c4*2+0] = packbf(v.x - hx, v.y - hy);
            Alo[row][c4*2+1] = packbf(v.z - hz, v.w - hw);
        }
        // ---- W tile: 32 k x 64 n -> [n][k-pair] ----
        {
            int j = tid >> 4, n4 = tid & 15;     // k-pair j (0..15), n base n4*4
            float4 w0 = *(const float4*)&W[(kk + 2*j)     * 64 + n4 * 4];
            float4 w1 = *(const float4*)&W[(kk + 2*j + 1) * 64 + n4 * 4];
            const float e0[4] = {w0.x, w0.y, w0.z, w0.w};
            const float e1[4] = {w1.x, w1.y, w1.z, w1.w};
            #pragma unroll
            for (int i = 0; i < 4; i++) {
                float h0 = __bfloat162float(__float2bfloat16(e0[i]));
                float h1 = __bfloat162float(__float2bfloat16(e1[i]));
                Bhi[n4*4 + i][j] = packbf(h0, h1);
                Blo[n4*4 + i][j] = packbf(e0[i] - h0, e1[i] - h1);
            }
        }
        __syncthreads();
        // ---- compute: two k16 sub-steps ----
        #pragma unroll
        for (int sub = 0; sub < 2; sub++) {
            int po = sub * 8;
            uint32_t ah[4], al[4];
            ah[0] = Ahi[wrow + g    ][po + tg];
            ah[1] = Ahi[wrow + g + 8][po + tg];
            ah[2] = Ahi[wrow + g    ][po + tg + 4];
            ah[3] = Ahi[wrow + g + 8][po + tg + 4];
            al[0] = Alo[wrow + g    ][po + tg];
            al[1] = Alo[wrow + g + 8][po + tg];
            al[2] = Alo[wrow + g    ][po + tg + 4];
            al[3] = Alo[wrow + g + 8][po + tg + 4];
            #pragma unroll
            for (int t = 0; t < 8; t++) {
                uint32_t bh[2], bl[2];
                bh[0] = Bhi[t*8 + g][po + tg];
                bh[1] = Bhi[t*8 + g][po + tg + 4];
                bl[0] = Blo[t*8 + g][po + tg];
                bl[1] = Blo[t*8 + g][po + tg + 4];
                mma_bf16(c[t], ah, bh);
                mma_bf16(c[t], ah, bl);
                mma_bf16(c[t], al, bh);
            }
        }
    }

    // ---- epilogue: store h1 + fused alpha projections ----
    int row0 = m0 + wrow + g;
    int row1 = row0 + 8;
    #pragma unroll
    for (int t = 0; t < 8; t++) {
        if (row0 < N)
            *(float2*)&g_h1[row0 * 64 + t*8 + tg*2] = make_float2(c[t][0], c[t][1]);
        if (row1 < N)
            *(float2*)&g_h1[row1 * 64 + t*8 + tg*2] = make_float2(c[t][2], c[t][3]);
        float as = sA[t*8 + tg*2], as2v = sA[t*8 + tg*2 + 1];
        float ad = sD[t*8 + tg*2], ad2v = sD[t*8 + tg*2 + 1];
        float s0 = c[t][0]*as + c[t][1]*as2v;   // row0
        float d0 = c[t][0]*ad + c[t][1]*ad2v;
        float s1 = c[t][2]*as + c[t][3]*as2v;   // row1
        float d1 = c[t][2]*ad + c[t][3]*ad2v;
        #pragma unroll
        for (int o = 1; o <= 2; o <<= 1) {
            s0 += __shfl_xor_sync(0xffffffffu, s0, o);
            d0 += __shfl_xor_sync(0xffffffffu, d0, o);
            s1 += __shfl_xor_sync(0xffffffffu, s1, o);
            d1 += __shfl_xor_sync(0xffffffffu, d1, o);
        }
        if (tg == 0) {
            if (row0 < N) { g_as1[row0 * 8 + t] = s0; g_ad1[row0 * 8 + t] = d0; }
            if (row1 < N) { g_as1[row1 * 8 + t] = s1; g_ad1[row1 * 8 + t] = d1; }
        }
    }
}

// -------- aggregation layer 1 (warp per dst, CSR, no atomics) -------------
__global__ void k_agg1(const float* __restrict__ b1, int N) {
    int d = (blockIdx.x * blockDim.x + threadIdx.x) >> 5;
    int lane = threadIdx.x & 31;
    if (d >= N) return;
    int beg = g_off[d], end = g_off[d + 1];
    float ad_l = (lane < NH) ? g_ad1[d * NH + lane] : 0.f;
    float accx = 0.f, accy = 0.f, den = 0.f;
    for (int i = beg; i < end; i++) {
        int s = g_csr[i];
        float w = 0.f;
        if (lane < NH) {
            float e = g_as1[s * NH + lane] + ad_l;
            e = e > 0.f ? e : 0.2f * e;          // LeakyReLU(0.2)
            w = __expf(e);
            den += w;
        }
        float wl = __shfl_sync(0xffffffffu, w, lane >> 2);   // head of 2*lane
        float2 hv = *(const float2*)&g_h1[s * 64 + lane * 2];
        accx += wl * hv.x;
        accy += wl * hv.y;
    }
    float denl = __shfl_sync(0xffffffffu, den, lane >> 2);
    float v0 = accx / denl + b1[2 * lane];
    float v1 = accy / denl + b1[2 * lane + 1];
    v0 = v0 > 0.f ? v0 : expm1f(v0);         // ELU
    v1 = v1 > 0.f ? v1 : expm1f(v1);
    *(float2*)&g_x2[d * 64 + 2 * lane] = make_float2(v0, v1);
}

// -------- GEMM2 + alpha projections layer 2 (warp per node) ---------------
__global__ void k_gemm2(const float* __restrict__ W2,
                        const float* __restrict__ a_src2,
                        const float* __restrict__ a_dst2, int N) {
    int wid = (blockIdx.x * blockDim.x + threadIdx.x) >> 5;
    int lane = threadIdx.x & 31;
    if (wid >= N) return;
    float v0 = g_x2[wid * 64 + lane];
    float v1 = g_x2[wid * 64 + 32 + lane];
    float asum = 0.f, adsum = 0.f;
    #pragma unroll
    for (int c = 0; c < NC; c++) {
        float s = v0 * W2[lane * NC + c] + v1 * W2[(lane + 32) * NC + c];
        #pragma unroll
        for (int o = 16; o; o >>= 1) s += __shfl_down_sync(0xffffffffu, s, o);
        if (lane == 0) {
            g_h2[wid * NC + c] = s;
            asum  += s * a_src2[c];
            adsum += s * a_dst2[c];
        }
    }
    if (lane == 0) { g_as2[wid] = asum; g_ad2[wid] = adsum; }
}

// -------- aggregation layer 2 (warp per dst, lanes over edges) ------------
__global__ void k_agg2(const float* __restrict__ b2, float* __restrict__ out, int N) {
    int d = (blockIdx.x * blockDim.x + threadIdx.x) >> 5;
    int lane = threadIdx.x & 31;
    if (d >= N) return;
    int beg = g_off[d], end = g_off[d + 1];
    float ad_d = g_ad2[d];
    float acc[NC] = {};
    float den = 0.f;
    for (int i = beg + lane; i < end; i += 32) {
        int s = g_csr[i];
        float e = g_as2[s] + ad_d;
        e = e > 0.f ? e : 0.2f * e;
        float w = __expf(e);
        den += w;
        const float* hp = &g_h2[s * NC];
        #pragma unroll
        for (int c = 0; c < NC; c++) acc[c] += w * hp[c];
    }
    #pragma unroll
    for (int o = 16; o; o >>= 1) {
        den += __shfl_down_sync(0xffffffffu, den, o);
        #pragma unroll
        for (int c = 0; c < NC; c++)
            acc[c] += __shfl_down_sync(0xffffffffu, acc[c], o);
    }
    if (lane == 0) {
        float inv = 1.f / den;
        float v[NC], m = -1e30f;
        #pragma unroll
        for (int c = 0; c < NC; c++) {
            v[c] = acc[c] * inv + b2[c];
            m = fmaxf(m, v[c]);
        }
        float ssum = 0.f;
        #pragma unroll
        for (int c = 0; c < NC; c++) ssum += __expf(v[c] - m);
        float l = __logf(ssum);
        #pragma unroll
        for (int c = 0; c < NC; c++) out[d * NC + c] = v[c] - m - l;
    }
}

// ---------------------------------------------------------------------------
// Fork/join launcher: the CSR-build chain (edge_index only) runs on a side
// stream concurrently with k_gemm1 (x/W1 only); they join before k_agg1.
// Capture-legal: event record on the capture stream + StreamWaitEvent forks
// the side stream into the same capture graph; the join wait merges it back.
extern "C" void kernel_launch(void* const* d_in, const int* in_sizes, int n_in,
                              void* d_out, int out_size) {
    const float* x   = (const float*)d_in[0];
    const void*  ei  = d_in[1];
    const float* W1  = (const float*)d_in[2];
    const float* as1 = (const float*)d_in[3];
    const float* ad1 = (const float*)d_in[4];
    const float* b1  = (const float*)d_in[5];
    const float* W2  = (const float*)d_in[6];
    const float* as2 = (const float*)d_in[7];
    const float* ad2 = (const float*)d_in[8];
    const float* b2  = (const float*)d_in[9];

    int       N  = in_sizes[0] / FF;           // 50000
    long long E  = (long long)in_sizes[1] / 2; // 1.6M
    long long EN = E + (long long)N;
    int nb = (N + SCANB - 1) / SCANB;
    float* out = (float*)d_out;

    cudaStream_t s1 = 0;
    cudaEvent_t ev0 = 0, ev1 = 0;
    bool forked =
        cudaStreamCreateWithFlags(&s1, cudaStreamNonBlocking) == cudaSuccess &&
        cudaEventCreateWithFlags(&ev0, cudaEventDisableTiming) == cudaSuccess &&
        cudaEventCreateWithFlags(&ev1, cudaEventDisableTiming) == cudaSuccess;

    if (forked) forked = cudaEventRecord(ev0, 0) == cudaSuccess &&
                         cudaStreamWaitEvent(s1, ev0, 0) == cudaSuccess;

    cudaStream_t cs = forked ? s1 : 0;   // CSR chain stream (falls back serial)

    // ---- branch A: CSR build (depends only on edge_index) ----
    k_detect<<<1, 32, 0, cs>>>((const long long*)ei, E, N);
    k_zero<<<(N + 255) / 256, 256, 0, cs>>>(N);
    k_hist<<<(unsigned)((EN + 255) / 256), 256, 0, cs>>>(ei, E, N);
    k_scan1<<<nb, SCANB, 0, cs>>>(N);
    k_scan2<<<1, SCANB, 0, cs>>>(nb);
    k_scan3<<<nb, SCANB, 0, cs>>>(N, (int)EN);
    k_scatter<<<(unsigned)((EN + 255) / 256), 256, 0, cs>>>(ei, E, N);
    if (forked) forked = cudaEventRecord(ev1, s1) == cudaSuccess;

    // ---- branch B: projection GEMM (depends only on x, W1) ----
    k_gemm1<<<(N + 127) / 128, 256>>>(x, W1, as1, ad1, N);

    // ---- join, then the dependent tail ----
    if (forked) cudaStreamWaitEvent(0, ev1, 0);

    k_agg1<<<(unsigned)(((long long)N * 32 + 255) / 256), 256>>>(b1, N);
    k_gemm2<<<(unsigned)(((long long)N * 32 + 255) / 256), 256>>>(W2, as2, ad2, N);
    k_agg2<<<(unsigned)(((long long)N * 32 + 255) / 256), 256>>>(b2, out, N);
    // Streams/events are intentionally not destroyed here: destroying a
    // forked stream mid-capture is illegal, and kernel_launch is invoked only
    // O(1) times by the harness (host-side handles only, no device memory).
}